// round 10
// baseline (speedup 1.0000x reference)
#include <cuda_runtime.h>
#include <cuda_fp16.h>

typedef unsigned int u32;

#define B_    512
#define ROWS  65536   // B_*128

// ---------------------------------------------------------------------------
// Device-global scratch (allocation-free rule)
// ---------------------------------------------------------------------------
__device__ __half g_A_hi[(size_t)B_ * 128 * 128];
__device__ __half g_A_lo[(size_t)B_ * 128 * 128];
__device__ __half g_Xt[(size_t)B_ * 256 * 128];     // [b][feat][tok]
__device__ __half g_Ht[(size_t)B_ * 256 * 128];
__device__ __half g_C_hi[(size_t)ROWS * 512];       // [row][0:256]=AX,[256:512]=AH
__device__ __half g_C_lo[(size_t)ROWS * 512];
__device__ float  g_Z[(size_t)ROWS * 256];
__device__ float  g_R[(size_t)ROWS * 256];
__device__ __half g_Wz[256 * 512];                  // [n][k] k<256: Wz1^T, k>=256: Wz2^T
__device__ __half g_Wr[256 * 512];
__device__ __half g_Wh1[256 * 256];
__device__ __half g_Wh2[256 * 256];

// ---------------------------------------------------------------------------
// Helpers
// ---------------------------------------------------------------------------
__device__ __forceinline__ u32 smem_u32(const void* p) {
    u32 a;
    asm("{ .reg .u64 t; cvta.to.shared.u64 t, %1; cvt.u32.u64 %0, t; }" : "=r"(a) : "l"(p));
    return a;
}
__device__ __forceinline__ void ldsm4(u32* r, u32 addr) {
    asm volatile("ldmatrix.sync.aligned.m8n8.x4.shared.b16 {%0,%1,%2,%3}, [%4];"
                 : "=r"(r[0]), "=r"(r[1]), "=r"(r[2]), "=r"(r[3]) : "r"(addr));
}
__device__ __forceinline__ void mma16816(float* d, const u32* a, const u32* b) {
    asm volatile(
        "mma.sync.aligned.m16n8k16.row.col.f32.f16.f16.f32 "
        "{%0,%1,%2,%3}, {%4,%5,%6,%7}, {%8,%9}, {%0,%1,%2,%3};"
        : "+f"(d[0]), "+f"(d[1]), "+f"(d[2]), "+f"(d[3])
        : "r"(a[0]), "r"(a[1]), "r"(a[2]), "r"(a[3]), "r"(b[0]), "r"(b[1]));
}
__device__ __forceinline__ float sigmoidf_fast(float x) {
    return 1.0f / (1.0f + __expf(-x));
}
__device__ __forceinline__ void split2(float x, __half& h, __half& l) {
    h = __float2half_rn(x);
    l = __float2half_rn(x - __half2float(h));
}
__device__ __forceinline__ void cp16(u32 sdst, const void* gsrc) {
    asm volatile(
        "{ .reg .u64 p; cvta.to.global.u64 p, %1; cp.async.cg.shared.global [%0], [p], 16; }"
        :: "r"(sdst), "l"(gsrc) : "memory");
}
__device__ __forceinline__ void cp_commit() {
    asm volatile("cp.async.commit_group;" ::: "memory");
}
template <int N>
__device__ __forceinline__ void cp_wait() {
    asm volatile("cp.async.wait_group %0;" :: "n"(N) : "memory");
}
// tail-aware wait: group `ch` must be complete; loads issued through min(NC,ch+3)
__device__ __forceinline__ void cp_wait_for(int ch, int NC) {
    if (ch <= NC - 3)      cp_wait<2>();
    else if (ch == NC - 2) cp_wait<1>();
    else                   cp_wait<0>();
}

// Tiles: rows x 32 halfs, padded to 80 B/row
#define STRB 80
#define OFF_AHI 0
#define OFF_ALO 10240     // 128*80
#define OFF_B   20480     // up to 256*80 B tile
#define STAGE_SZ 40960
#define NSTAGE   4
#define SMEM_TOTAL (STAGE_SZ * NSTAGE)   // 163840; 1 CTA/SM (512 thr, 16 warps)

// Async-copy a [rows x 32] half tile (global stride gs halfs). 512 threads.
__device__ __forceinline__ void cp_tile(u32 sdst, const __half* g, int rows, int gs, int tid) {
    int total = rows * 4;
    for (int i = tid; i < total; i += 512) {
        int r = i >> 2, c = i & 3;
        cp16(sdst + r * STRB + c * 16, g + (size_t)r * gs + c * 8);
    }
}

// ---------------------------------------------------------------------------
// Conversion kernels (256 threads each)
// ---------------------------------------------------------------------------
__global__ __launch_bounds__(256) void conv_A(const float* __restrict__ A) {
    size_t i = ((size_t)blockIdx.x * 256 + threadIdx.x) * 4;
    float4 v = *(const float4*)(A + i);
    __half h0, h1, h2, h3, l0, l1, l2, l3;
    split2(v.x, h0, l0); split2(v.y, h1, l1); split2(v.z, h2, l2); split2(v.w, h3, l3);
    __half2 hv0 = __halves2half2(h0, h1), hv1 = __halves2half2(h2, h3);
    __half2 lv0 = __halves2half2(l0, l1), lv1 = __halves2half2(l2, l3);
    *(uint2*)(g_A_hi + i) = make_uint2(*(u32*)&hv0, *(u32*)&hv1);
    *(uint2*)(g_A_lo + i) = make_uint2(*(u32*)&lv0, *(u32*)&lv1);
}

__global__ __launch_bounds__(256) void conv_XH(const float* __restrict__ X,
                                               const float* __restrict__ Hd) {
    int z = blockIdx.z;
    int b = z & (B_ - 1);
    const float* src = (z < B_) ? X : Hd;
    __half* dst = (z < B_) ? g_Xt : g_Ht;
    __shared__ float s[32][33];
    int tx = threadIdx.x & 31, ty = threadIdx.x >> 5;
    int f0 = blockIdx.x * 32, t0 = blockIdx.y * 32;
    const float* sp = src + (size_t)b * 128 * 256;
#pragma unroll
    for (int r = 0; r < 4; r++)
        s[ty + 8 * r][tx] = sp[(size_t)(t0 + ty + 8 * r) * 256 + f0 + tx];
    __syncthreads();
    size_t dbase = (size_t)b * 256 * 128;
#pragma unroll
    for (int r = 0; r < 4; r++)
        dst[dbase + (size_t)(f0 + ty + 8 * r) * 128 + t0 + tx] =
            __float2half_rn(s[tx][ty + 8 * r]);
}

__global__ __launch_bounds__(256) void conv_W(const float* __restrict__ Wz1, const float* __restrict__ Wz2,
                                              const float* __restrict__ Wr1, const float* __restrict__ Wr2,
                                              const float* __restrict__ Wh1, const float* __restrict__ Wh2) {
    int job = blockIdx.z;
    const float* src; __half* dst; int koff, stride;
    switch (job) {
        case 0:  src = Wz1; dst = g_Wz;  koff = 0;   stride = 512; break;
        case 1:  src = Wz2; dst = g_Wz;  koff = 256; stride = 512; break;
        case 2:  src = Wr1; dst = g_Wr;  koff = 0;   stride = 512; break;
        case 3:  src = Wr2; dst = g_Wr;  koff = 256; stride = 512; break;
        case 4:  src = Wh1; dst = g_Wh1; koff = 0;   stride = 256; break;
        default: src = Wh2; dst = g_Wh2; koff = 0;   stride = 256; break;
    }
    __shared__ float s[32][33];
    int tx = threadIdx.x & 31, ty = threadIdx.x >> 5;
    int n0 = blockIdx.x * 32, k0 = blockIdx.y * 32;
#pragma unroll
    for (int r = 0; r < 4; r++)
        s[ty + 8 * r][tx] = src[(size_t)(k0 + ty + 8 * r) * 256 + n0 + tx];
    __syncthreads();
#pragma unroll
    for (int r = 0; r < 4; r++)
        dst[(size_t)(n0 + ty + 8 * r) * stride + koff + k0 + tx] =
            __float2half_rn(s[tx][ty + 8 * r]);
}

// ---------------------------------------------------------------------------
// MMA warp tile 32(M) x 64(N), K=32, split-A 2-term. B frags from boff.
// ---------------------------------------------------------------------------
__device__ __forceinline__ void mma_w64(float acc[2][8][4], u32 sbuf,
                                        u32 aoff, u32 boff) {
#pragma unroll
    for (int k16 = 0; k16 < 2; k16++) {
        u32 bf[4][4];
#pragma unroll
        for (int q = 0; q < 4; q++)
            ldsm4(bf[q], sbuf + OFF_B + boff + q * (16 * STRB) + k16 * 32);
        u32 ah[2][4], al[2][4];
#pragma unroll
        for (int mi = 0; mi < 2; mi++) {
            ldsm4(ah[mi], sbuf + OFF_AHI + aoff + mi * 16 * STRB + k16 * 32);
            ldsm4(al[mi], sbuf + OFF_ALO + aoff + mi * 16 * STRB + k16 * 32);
        }
#pragma unroll
        for (int mi = 0; mi < 2; mi++)
#pragma unroll
            for (int ni = 0; ni < 8; ni++)
                mma16816(acc[mi][ni], ah[mi], &bf[ni >> 1][(ni & 1) * 2]);
#pragma unroll
        for (int mi = 0; mi < 2; mi++)
#pragma unroll
            for (int ni = 0; ni < 8; ni++)
                mma16816(acc[mi][ni], al[mi], &bf[ni >> 1][(ni & 1) * 2]);
    }
}

#define ZERO_ACC8(acc) \
    _Pragma("unroll") for (int _a = 0; _a < 2; _a++) \
    _Pragma("unroll") for (int _c = 0; _c < 8; _c++) \
    _Pragma("unroll") for (int _d = 0; _d < 4; _d++) acc[_a][_c][_d] = 0.0f;
#define ZERO_ACC4(acc) \
    _Pragma("unroll") for (int _a = 0; _a < 2; _a++) \
    _Pragma("unroll") for (int _c = 0; _c < 4; _c++) \
    _Pragma("unroll") for (int _d = 0; _d < 4; _d++) acc[_a][_c][_d] = 0.0f;

// ---------------------------------------------------------------------------
// k1: per (nb, b): C[128 tok, 256 cols] = [X feats nb*128.. | H feats nb*128..]
// 512 thr, 16 warps 4Mx4N, warp 32x64. grid (2, 512). 4 chunks.
// ---------------------------------------------------------------------------
__global__ __launch_bounds__(512, 1) void k1() {
    extern __shared__ char sm[];
    const int tid = threadIdx.x, lane = tid & 31, wid = tid >> 5;
    const int wm = wid >> 2, wn = wid & 3;
    const int nb = blockIdx.x, b = blockIdx.y;

    const __half* Ah = g_A_hi + (size_t)b * 16384;
    const __half* Al = g_A_lo + (size_t)b * 16384;
    const __half* Bx = g_Xt + (size_t)b * 32768 + (size_t)nb * 128 * 128;
    const __half* Bh = g_Ht + (size_t)b * 32768 + (size_t)nb * 128 * 128;

    const u32 sb = smem_u32(sm);
    const u32 aoff = (u32)((wm * 32 + (lane & 15)) * STRB + (lane >> 4) * 16);
    const u32 boff = (u32)((wn * 64 + (lane & 7) + ((lane >> 4) << 3)) * STRB + ((lane >> 3) & 1) * 16);

    float acc[2][8][4];
    ZERO_ACC8(acc);

    // B tile: rows 0-127 = X feats, 128-255 = H feats
    auto load = [&](int ch, u32 st) {
        cp_tile(st + OFF_AHI, Ah + ch * 32, 128, 128, tid);
        cp_tile(st + OFF_ALO, Al + ch * 32, 128, 128, tid);
        cp_tile(st + OFF_B,              Bx + ch * 32, 128, 128, tid);
        cp_tile(st + OFF_B + 128 * STRB, Bh + ch * 32, 128, 128, tid);
    };

    load(0, sb); cp_commit();
    load(1, sb + STAGE_SZ); cp_commit();
    load(2, sb + 2 * STAGE_SZ); cp_commit();

    const int NC = 4;
    for (int ch = 0; ch < NC; ch++) {
        cp_wait_for(ch, NC);
        __syncthreads();
        if (ch + 3 < NC) { load(ch + 3, sb + ((ch + 3) & 3) * STAGE_SZ); cp_commit(); }
        mma_w64(acc, sb + (ch & 3) * STAGE_SZ, aoff, boff);
    }

    const size_t rowbase = (size_t)b * 128;
    const int colb = (wn < 2) ? (nb * 128 + wn * 64) : (256 + nb * 128 + (wn - 2) * 64);
#pragma unroll
    for (int mi = 0; mi < 2; mi++)
#pragma unroll
        for (int ni = 0; ni < 8; ni++)
#pragma unroll
            for (int hh = 0; hh < 2; hh++) {
                size_t row = rowbase + wm * 32 + mi * 16 + (lane >> 2) + hh * 8;
                int c = colb + ni * 8 + (lane & 3) * 2;
                float x0 = acc[mi][ni][hh * 2], x1 = acc[mi][ni][hh * 2 + 1];
                __half h0, l0, h1, l1;
                split2(x0, h0, l0); split2(x1, h1, l1);
                *(__half2*)(g_C_hi + row * 512 + c) = __halves2half2(h0, h1);
                *(__half2*)(g_C_lo + row * 512 + c) = __halves2half2(l0, l1);
            }
}

// ---------------------------------------------------------------------------
// k2 dual-gate: Z AND R = sigmoid(C @ W^T + bias) for a 128x128 tile.
// C staged once per chunk for both gates. 512 thr, warp 32x32 per gate.
// grid (2, 512): x = nb, y = rt. 16 chunks (K=512).
// ---------------------------------------------------------------------------
__global__ __launch_bounds__(512, 1) void k2(const float* __restrict__ bias_z,
                                             const float* __restrict__ bias_r) {
    extern __shared__ char sm[];
    const int tid = threadIdx.x, lane = tid & 31, wid = tid >> 5;
    const int wm = wid >> 2, wn = wid & 3;
    const int nb = blockIdx.x, rt = blockIdx.y;

    const __half* Ah = g_C_hi + (size_t)rt * 128 * 512;
    const __half* Al = g_C_lo + (size_t)rt * 128 * 512;
    const __half* Bz = g_Wz + (size_t)nb * 128 * 512;
    const __half* Br = g_Wr + (size_t)nb * 128 * 512;

    const u32 sb = smem_u32(sm);
    const u32 aoff = (u32)((wm * 32 + (lane & 15)) * STRB + (lane >> 4) * 16);
    // b tile rows: 0-127 = Wz slice, 128-255 = Wr slice
    const u32 boffz = (u32)((wn * 32 + (lane & 7) + ((lane >> 4) << 3)) * STRB + ((lane >> 3) & 1) * 16);
    const u32 boffr = boffz + 128 * STRB;

    float accz[2][4][4], accr[2][4][4];
    ZERO_ACC4(accz); ZERO_ACC4(accr);

    auto load = [&](int ch, u32 st) {
        cp_tile(st + OFF_AHI, Ah + ch * 32, 128, 512, tid);
        cp_tile(st + OFF_ALO, Al + ch * 32, 128, 512, tid);
        cp_tile(st + OFF_B,              Bz + ch * 32, 128, 512, tid);
        cp_tile(st + OFF_B + 128 * STRB, Br + ch * 32, 128, 512, tid);
    };

    load(0, sb); cp_commit();
    load(1, sb + STAGE_SZ); cp_commit();
    load(2, sb + 2 * STAGE_SZ); cp_commit();

    const int NC = 16;
    for (int ch = 0; ch < NC; ch++) {
        cp_wait_for(ch, NC);
        __syncthreads();
        if (ch + 3 < NC) { load(ch + 3, sb + ((ch + 3) & 3) * STAGE_SZ); cp_commit(); }
        u32 sbuf = sb + (ch & 3) * STAGE_SZ;
#pragma unroll
        for (int k16 = 0; k16 < 2; k16++) {
            u32 bfz[2][4], bfr[2][4];
#pragma unroll
            for (int q = 0; q < 2; q++) {
                ldsm4(bfz[q], sbuf + OFF_B + boffz + q * (16 * STRB) + k16 * 32);
                ldsm4(bfr[q], sbuf + OFF_B + boffr + q * (16 * STRB) + k16 * 32);
            }
            u32 ah[2][4], al[2][4];
#pragma unroll
            for (int mi = 0; mi < 2; mi++) {
                ldsm4(ah[mi], sbuf + OFF_AHI + aoff + mi * 16 * STRB + k16 * 32);
                ldsm4(al[mi], sbuf + OFF_ALO + aoff + mi * 16 * STRB + k16 * 32);
            }
#pragma unroll
            for (int mi = 0; mi < 2; mi++)
#pragma unroll
                for (int ni = 0; ni < 4; ni++) {
                    mma16816(accz[mi][ni], ah[mi], &bfz[ni >> 1][(ni & 1) * 2]);
                    mma16816(accr[mi][ni], ah[mi], &bfr[ni >> 1][(ni & 1) * 2]);
                }
#pragma unroll
            for (int mi = 0; mi < 2; mi++)
#pragma unroll
                for (int ni = 0; ni < 4; ni++) {
                    mma16816(accz[mi][ni], al[mi], &bfz[ni >> 1][(ni & 1) * 2]);
                    mma16816(accr[mi][ni], al[mi], &bfr[ni >> 1][(ni & 1) * 2]);
                }
        }
    }

#pragma unroll
    for (int mi = 0; mi < 2; mi++)
#pragma unroll
        for (int ni = 0; ni < 4; ni++)
#pragma unroll
            for (int hh = 0; hh < 2; hh++) {
                int lr = wm * 32 + mi * 16 + (lane >> 2) + hh * 8;
                int c  = nb * 128 + wn * 32 + ni * 8 + (lane & 3) * 2;
                size_t go = ((size_t)rt * 128 + lr) * 256 + c;
                float2 bbz = *(const float2*)(bias_z + (size_t)lr * 256 + c);
                float2 bbr = *(const float2*)(bias_r + (size_t)lr * 256 + c);
                float2 oz, orr;
                oz.x  = sigmoidf_fast(accz[mi][ni][hh * 2]     + bbz.x);
                oz.y  = sigmoidf_fast(accz[mi][ni][hh * 2 + 1] + bbz.y);
                orr.x = sigmoidf_fast(accr[mi][ni][hh * 2]     + bbr.x);
                orr.y = sigmoidf_fast(accr[mi][ni][hh * 2 + 1] + bbr.y);
                *(float2*)(g_Z + go) = oz;
                *(float2*)(g_R + go) = orr;
            }
}

// ---------------------------------------------------------------------------
// k3: acc = AH@Wh2 (8 chunks); acc *= r; acc += AX@Wh1 (8 chunks);
//     out = z*h + (1-z)*tanh(acc + bh). N=256 per CTA. grid (512).
// ---------------------------------------------------------------------------
__global__ __launch_bounds__(512, 1) void k3(const float* __restrict__ bias_h,
                                             const float* __restrict__ hidden,
                                             float* __restrict__ Out) {
    extern __shared__ char sm[];
    const int tid = threadIdx.x, lane = tid & 31, wid = tid >> 5;
    const int wm = wid >> 2, wn = wid & 3;
    const int rt = blockIdx.x;

    const __half* Ah = g_C_hi + (size_t)rt * 128 * 512;
    const __half* Al = g_C_lo + (size_t)rt * 128 * 512;

    const u32 sb = smem_u32(sm);
    const u32 aoff = (u32)((wm * 32 + (lane & 15)) * STRB + (lane >> 4) * 16);
    const u32 boff = (u32)((wn * 64 + (lane & 7) + ((lane >> 4) << 3)) * STRB + ((lane >> 3) & 1) * 16);

    float acc[2][8][4];
    ZERO_ACC8(acc);

    // chunk j: j<8 -> A cols 256+j*32 with Wh2 ; j>=8 -> A cols (j-8)*32 with Wh1
    auto load = [&](int j, u32 st) {
        int acol = (j < 8) ? (256 + j * 32) : ((j - 8) * 32);
        const __half* Bn = ((j < 8) ? g_Wh2 : g_Wh1) + ((j < 8) ? j : (j - 8)) * 32;
        cp_tile(st + OFF_AHI, Ah + acol, 128, 512, tid);
        cp_tile(st + OFF_ALO, Al + acol, 128, 512, tid);
        cp_tile(st + OFF_B,   Bn, 256, 256, tid);
    };

    load(0, sb); cp_commit();
    load(1, sb + STAGE_SZ); cp_commit();
    load(2, sb + 2 * STAGE_SZ); cp_commit();

    const int NC = 16;
    for (int j = 0; j < NC; j++) {
        cp_wait_for(j, NC);
        __syncthreads();
        if (j + 3 < NC) { load(j + 3, sb + ((j + 3) & 3) * STAGE_SZ); cp_commit(); }
        mma_w64(acc, sb + (j & 3) * STAGE_SZ, aoff, boff);
        if (j == 7) {
#pragma unroll
            for (int mi = 0; mi < 2; mi++)
#pragma unroll
                for (int ni = 0; ni < 8; ni++)
#pragma unroll
                    for (int hh = 0; hh < 2; hh++) {
                        int lr = wm * 32 + mi * 16 + (lane >> 2) + hh * 8;
                        int c  = wn * 64 + ni * 8 + (lane & 3) * 2;
                        float2 rv = *(const float2*)(g_R + ((size_t)rt * 128 + lr) * 256 + c);
                        acc[mi][ni][hh * 2]     *= rv.x;
                        acc[mi][ni][hh * 2 + 1] *= rv.y;
                    }
        }
    }

#pragma unroll
    for (int mi = 0; mi < 2; mi++)
#pragma unroll
        for (int ni = 0; ni < 8; ni++)
#pragma unroll
            for (int hh = 0; hh < 2; hh++) {
                int lr = wm * 32 + mi * 16 + (lane >> 2) + hh * 8;
                int c  = wn * 64 + ni * 8 + (lane & 3) * 2;
                size_t off = ((size_t)rt * 128 + lr) * 256 + c;
                float2 zv = *(const float2*)(g_Z + off);
                float2 hv = *(const float2*)(hidden + off);
                float2 bv = *(const float2*)(bias_h + (size_t)lr * 256 + c);
                float t0 = tanhf(acc[mi][ni][hh * 2]     + bv.x);
                float t1 = tanhf(acc[mi][ni][hh * 2 + 1] + bv.y);
                float2 o;
                o.x = zv.x * hv.x + (1.0f - zv.x) * t0;
                o.y = zv.y * hv.y + (1.0f - zv.y) * t1;
                *(float2*)(Out + off) = o;
            }
}

// ---------------------------------------------------------------------------
extern "C" void kernel_launch(void* const* d_in, const int* in_sizes, int n_in,
                              void* d_out, int out_size) {
    (void)in_sizes; (void)n_in; (void)out_size;
    const float* X      = (const float*)d_in[0];
    const float* A      = (const float*)d_in[1];
    const float* hidden = (const float*)d_in[2];
    const float* Wz1    = (const float*)d_in[3];
    const float* Wz2    = (const float*)d_in[4];
    const float* Wr1    = (const float*)d_in[5];
    const float* Wr2    = (const float*)d_in[6];
    const float* Wh1    = (const float*)d_in[7];
    const float* Wh2    = (const float*)d_in[8];
    const float* bz     = (const float*)d_in[9];
    const float* br     = (const float*)d_in[10];
    const float* bh     = (const float*)d_in[11];
    float* out          = (float*)d_out;

    static bool attr_done = false;
    if (!attr_done) {
        cudaFuncSetAttribute(k1, cudaFuncAttributeMaxDynamicSharedMemorySize, SMEM_TOTAL);
        cudaFuncSetAttribute(k2, cudaFuncAttributeMaxDynamicSharedMemorySize, SMEM_TOTAL);
        cudaFuncSetAttribute(k3, cudaFuncAttributeMaxDynamicSharedMemorySize, SMEM_TOTAL);
        attr_done = true;
    }

    conv_A<<<8192, 256>>>(A);
    conv_XH<<<dim3(8, 4, 1024), 256>>>(X, hidden);
    conv_W<<<dim3(8, 8, 6), 256>>>(Wz1, Wz2, Wr1, Wr2, Wh1, Wh2);

    k1<<<dim3(2, 512), 512, SMEM_TOTAL>>>();
    k2<<<dim3(2, 512), 512, SMEM_TOTAL>>>(bz, br);
    k3<<<512, 512, SMEM_TOTAL>>>(bh, hidden, out);
}

// round 11
// speedup vs baseline: 1.2469x; 1.2469x over previous
#include <cuda_runtime.h>
#include <cuda_fp16.h>

typedef unsigned int u32;

#define B_    512
#define ROWS  65536   // B_*128

// ---------------------------------------------------------------------------
// Device-global scratch (allocation-free rule)
// g_C_hi/lo + g_Wz/g_Wr are BLOCKED: [tile][128 rows][32 halfs] = 8KB blocks,
// swizzled within block: byte = row*64 + ((col*2) ^ (((row>>1)&3)<<4)).
// ---------------------------------------------------------------------------
__device__ __align__(128) __half g_A_hi[(size_t)B_ * 128 * 128];
__device__ __align__(128) __half g_A_lo[(size_t)B_ * 128 * 128];
__device__ __align__(128) __half g_Xt[(size_t)B_ * 256 * 128];   // [b][feat][tok]
__device__ __align__(128) __half g_Ht[(size_t)B_ * 256 * 128];
__device__ __align__(128) __half g_C_hi[(size_t)ROWS * 512];     // blocked: [rt*16+kc][128][32]
__device__ __align__(128) __half g_C_lo[(size_t)ROWS * 512];
__device__ float  g_Z[(size_t)ROWS * 256];
__device__ float  g_R[(size_t)ROWS * 256];
__device__ __align__(128) __half g_Wz[256 * 512];   // blocked: [nb*16+kc][128 n][32 k]
__device__ __align__(128) __half g_Wr[256 * 512];
__device__ __half g_Wh1[256 * 256];                 // [n][k] (k3 path, unblocked)
__device__ __half g_Wh2[256 * 256];

// ---------------------------------------------------------------------------
// Helpers
// ---------------------------------------------------------------------------
__device__ __forceinline__ u32 smem_u32(const void* p) {
    u32 a;
    asm("{ .reg .u64 t; cvta.to.shared.u64 t, %1; cvt.u32.u64 %0, t; }" : "=r"(a) : "l"(p));
    return a;
}
__device__ __forceinline__ void ldsm4(u32* r, u32 addr) {
    asm volatile("ldmatrix.sync.aligned.m8n8.x4.shared.b16 {%0,%1,%2,%3}, [%4];"
                 : "=r"(r[0]), "=r"(r[1]), "=r"(r[2]), "=r"(r[3]) : "r"(addr));
}
__device__ __forceinline__ void mma16816(float* d, const u32* a, const u32* b) {
    asm volatile(
        "mma.sync.aligned.m16n8k16.row.col.f32.f16.f16.f32 "
        "{%0,%1,%2,%3}, {%4,%5,%6,%7}, {%8,%9}, {%0,%1,%2,%3};"
        : "+f"(d[0]), "+f"(d[1]), "+f"(d[2]), "+f"(d[3])
        : "r"(a[0]), "r"(a[1]), "r"(a[2]), "r"(a[3]), "r"(b[0]), "r"(b[1]));
}
__device__ __forceinline__ float sigmoidf_fast(float x) {
    return 1.0f / (1.0f + __expf(-x));
}
__device__ __forceinline__ void split2(float x, __half& h, __half& l) {
    h = __float2half_rn(x);
    l = __float2half_rn(x - __half2float(h));
}
__device__ __forceinline__ void cp16(u32 sdst, const void* gsrc) {
    asm volatile(
        "{ .reg .u64 p; cvta.to.global.u64 p, %1; cp.async.cg.shared.global [%0], [p], 16; }"
        :: "r"(sdst), "l"(gsrc) : "memory");
}
__device__ __forceinline__ void cp_commit() {
    asm volatile("cp.async.commit_group;" ::: "memory");
}
template <int N>
__device__ __forceinline__ void cp_wait() {
    asm volatile("cp.async.wait_group %0;" :: "n"(N) : "memory");
}
// ---- bulk DMA + mbarrier (base sm_90 PTX) ----
__device__ __forceinline__ void cp_bulk(u32 sdst, const void* gsrc, u32 bytes, u32 mbar) {
    asm volatile(
        "{ .reg .u64 p; cvta.to.global.u64 p, %1;\n\t"
        "cp.async.bulk.shared::cluster.global.mbarrier::complete_tx::bytes [%0], [p], %2, [%3]; }"
        :: "r"(sdst), "l"(gsrc), "r"(bytes), "r"(mbar) : "memory");
}
__device__ __forceinline__ void mbar_init(u32 addr, u32 cnt) {
    asm volatile("mbarrier.init.shared.b64 [%0], %1;" :: "r"(addr), "r"(cnt) : "memory");
}
__device__ __forceinline__ void mbar_expect(u32 addr, u32 bytes) {
    asm volatile("mbarrier.arrive.expect_tx.shared::cta.b64 _, [%0], %1;"
                 :: "r"(addr), "r"(bytes) : "memory");
}
__device__ __forceinline__ void mbar_wait(u32 addr, u32 parity) {
    asm volatile(
        "{\n\t.reg .pred P;\n\t"
        "WAIT_%=:\n\t"
        "mbarrier.try_wait.parity.acquire.cta.shared::cta.b64 P, [%0], %1, 0x989680;\n\t"
        "@!P bra.uni WAIT_%=;\n\t}"
        :: "r"(addr), "r"(parity) : "memory");
}

// Padded staging (k1, k3-B): rows x 32 halfs, 80 B/row
#define STRB 80

// cp.async a [rows x 32] half tile (global stride gs halfs). 256 threads.
__device__ __forceinline__ void cp_tile(u32 sdst, const __half* g, int rows, int gs, int tid) {
    int total = rows * 4;
    for (int i = tid; i < total; i += 256) {
        int r = i >> 2, c = i & 3;
        cp16(sdst + r * STRB + c * 16, g + (size_t)r * gs + c * 8);
    }
}
__device__ __forceinline__ void cp_tile128(u32 sdst, const __half* g, int rows, int gs, int t) {
    int total = rows * 4;
    for (int i = t; i < total; i += 128) {
        int r = i >> 2, c = i & 3;
        cp16(sdst + r * STRB + c * 16, g + (size_t)r * gs + c * 8);
    }
}

#define ZERO_ACC8(acc) \
    _Pragma("unroll") for (int _a = 0; _a < 2; _a++) \
    _Pragma("unroll") for (int _c = 0; _c < 8; _c++) \
    _Pragma("unroll") for (int _d = 0; _d < 4; _d++) acc[_a][_c][_d] = 0.0f;

// ---------------------------------------------------------------------------
// Conversion kernels
// ---------------------------------------------------------------------------
__global__ __launch_bounds__(256) void conv_A(const float* __restrict__ A) {
    size_t i = ((size_t)blockIdx.x * 256 + threadIdx.x) * 4;
    float4 v = *(const float4*)(A + i);
    __half h0, h1, h2, h3, l0, l1, l2, l3;
    split2(v.x, h0, l0); split2(v.y, h1, l1); split2(v.z, h2, l2); split2(v.w, h3, l3);
    __half2 hv0 = __halves2half2(h0, h1), hv1 = __halves2half2(h2, h3);
    __half2 lv0 = __halves2half2(l0, l1), lv1 = __halves2half2(l2, l3);
    *(uint2*)(g_A_hi + i) = make_uint2(*(u32*)&hv0, *(u32*)&hv1);
    *(uint2*)(g_A_lo + i) = make_uint2(*(u32*)&lv0, *(u32*)&lv1);
}

__global__ __launch_bounds__(256) void conv_XH(const float* __restrict__ X,
                                               const float* __restrict__ Hd) {
    int z = blockIdx.z;
    int b = z & (B_ - 1);
    const float* src = (z < B_) ? X : Hd;
    __half* dst = (z < B_) ? g_Xt : g_Ht;
    __shared__ float s[32][33];
    int tx = threadIdx.x & 31, ty = threadIdx.x >> 5;
    int f0 = blockIdx.x * 32, t0 = blockIdx.y * 32;
    const float* sp = src + (size_t)b * 128 * 256;
#pragma unroll
    for (int r = 0; r < 4; r++)
        s[ty + 8 * r][tx] = sp[(size_t)(t0 + ty + 8 * r) * 256 + f0 + tx];
    __syncthreads();
    size_t dbase = (size_t)b * 256 * 128;
#pragma unroll
    for (int r = 0; r < 4; r++)
        dst[dbase + (size_t)(f0 + ty + 8 * r) * 128 + t0 + tx] =
            __float2half_rn(s[tx][ty + 8 * r]);
}

// jobs 0-3 write BLOCKED+swizzled g_Wz/g_Wr; jobs 4-5 plain [n][k] Wh.
__global__ __launch_bounds__(256) void conv_W(const float* __restrict__ Wz1, const float* __restrict__ Wz2,
                                              const float* __restrict__ Wr1, const float* __restrict__ Wr2,
                                              const float* __restrict__ Wh1, const float* __restrict__ Wh2) {
    int job = blockIdx.z;
    const float* src; __half* dst; int koff; bool blocked;
    switch (job) {
        case 0:  src = Wz1; dst = g_Wz;  koff = 0;   blocked = true;  break;
        case 1:  src = Wz2; dst = g_Wz;  koff = 256; blocked = true;  break;
        case 2:  src = Wr1; dst = g_Wr;  koff = 0;   blocked = true;  break;
        case 3:  src = Wr2; dst = g_Wr;  koff = 256; blocked = true;  break;
        case 4:  src = Wh1; dst = g_Wh1; koff = 0;   blocked = false; break;
        default: src = Wh2; dst = g_Wh2; koff = 0;   blocked = false; break;
    }
    __shared__ float s[32][33];
    int tx = threadIdx.x & 31, ty = threadIdx.x >> 5;
    int n0 = blockIdx.x * 32, k0 = blockIdx.y * 32;
#pragma unroll
    for (int r = 0; r < 4; r++)
        s[ty + 8 * r][tx] = src[(size_t)(k0 + ty + 8 * r) * 256 + n0 + tx];
    __syncthreads();
#pragma unroll
    for (int r = 0; r < 4; r++) {
        int n = n0 + ty + 8 * r;
        int k = koff + k0 + tx;
        __half h = __float2half_rn(s[tx][ty + 8 * r]);
        if (blocked) {
            int nb = n >> 7, nr = n & 127, kc = k >> 5, kk = k & 31;
            size_t hidx = (size_t)(nb * 16 + kc) * 4096 + nr * 32
                        + ((((kk * 2) ^ (((nr >> 1) & 3) << 4))) >> 1);
            dst[hidx] = h;
        } else {
            dst[(size_t)n * 256 + k] = h;
        }
    }
}

// ---------------------------------------------------------------------------
// Padded-layout MMA chunk (k1): warp 32(M) x 64(N), K=32, split-A 2-term.
// ---------------------------------------------------------------------------
__device__ __forceinline__ void mma_w64_pad(float acc[2][8][4], u32 sA, u32 sL, u32 sB,
                                            u32 aoff, u32 boff) {
#pragma unroll
    for (int k16 = 0; k16 < 2; k16++) {
        u32 bf[4][4];
#pragma unroll
        for (int q = 0; q < 4; q++)
            ldsm4(bf[q], sB + boff + q * (16 * STRB) + k16 * 32);
        u32 ah[2][4], al[2][4];
#pragma unroll
        for (int mi = 0; mi < 2; mi++) {
            ldsm4(ah[mi], sA + aoff + mi * 16 * STRB + k16 * 32);
            ldsm4(al[mi], sL + aoff + mi * 16 * STRB + k16 * 32);
        }
#pragma unroll
        for (int mi = 0; mi < 2; mi++)
#pragma unroll
            for (int ni = 0; ni < 8; ni++)
                mma16816(acc[mi][ni], ah[mi], &bf[ni >> 1][(ni & 1) * 2]);
#pragma unroll
        for (int mi = 0; mi < 2; mi++)
#pragma unroll
            for (int ni = 0; ni < 8; ni++)
                mma16816(acc[mi][ni], al[mi], &bf[ni >> 1][(ni & 1) * 2]);
    }
}

// ---------------------------------------------------------------------------
// k1: per (nb, b): C[128 tok, 128 cols] (X feats nb*64.. | H feats nb*64..).
// R9 staging (cp.async, 3 stages); epilogue writes BLOCKED C. grid (4, 512).
// ---------------------------------------------------------------------------
#define K1_STAGE 30720
#define K1_SMEM  92160
__global__ __launch_bounds__(256, 2) void k1() {
    extern __shared__ char sm[];
    const int tid = threadIdx.x, lane = tid & 31, wid = tid >> 5;
    const int wm = wid >> 1, wn = wid & 1;
    const int nb = blockIdx.x, b = blockIdx.y;

    const __half* Ah = g_A_hi + (size_t)b * 16384;
    const __half* Al = g_A_lo + (size_t)b * 16384;
    const __half* Bx = g_Xt + (size_t)b * 32768 + (size_t)nb * 64 * 128;
    const __half* Bh = g_Ht + (size_t)b * 32768 + (size_t)nb * 64 * 128;

    const u32 sb = smem_u32(sm);
    const u32 aoff = (u32)((wm * 32 + (lane & 15)) * STRB + (lane >> 4) * 16);
    const u32 boff = (u32)((wn * 64 + (lane & 7) + ((lane >> 4) << 3)) * STRB + ((lane >> 3) & 1) * 16);

    float acc[2][8][4];
    ZERO_ACC8(acc);

    auto load = [&](int ch, u32 st) {
        cp_tile(st,         Ah + ch * 32, 128, 128, tid);
        cp_tile(st + 10240, Al + ch * 32, 128, 128, tid);
        if (tid < 128) cp_tile128(st + 20480,             Bx + ch * 32, 64, 128, tid);
        else           cp_tile128(st + 20480 + 64 * STRB, Bh + ch * 32, 64, 128, tid - 128);
    };

    load(0, sb); cp_commit();
    load(1, sb + K1_STAGE); cp_commit();

    const int NC = 4;
    for (int ch = 0; ch < NC; ch++) {
        if (ch < NC - 1) cp_wait<1>(); else cp_wait<0>();
        __syncthreads();
        if (ch + 2 < NC) { load(ch + 2, sb + ((ch + 2) % 3) * K1_STAGE); cp_commit(); }
        u32 st = sb + (ch % 3) * K1_STAGE;
        mma_w64_pad(acc, st, st + 10240, st + 20480, aoff, boff);
    }

    const size_t cb_base = (size_t)b * (16 * 4096);     // half units
    const int colb = (wn == 0) ? (nb * 64) : (256 + nb * 64);
#pragma unroll
    for (int mi = 0; mi < 2; mi++)
#pragma unroll
        for (int ni = 0; ni < 8; ni++)
#pragma unroll
            for (int hh = 0; hh < 2; hh++) {
                int lr = wm * 32 + mi * 16 + (lane >> 2) + hh * 8;
                int c  = colb + ni * 8 + (lane & 3) * 2;
                int kc = c >> 5, cc = c & 31;
                u32 swo = (u32)((cc * 2) ^ (((lr >> 1) & 3) << 4));
                size_t hidx = cb_base + (size_t)kc * 4096 + (size_t)lr * 32 + (swo >> 1);
                float x0 = acc[mi][ni][hh * 2], x1 = acc[mi][ni][hh * 2 + 1];
                __half h0, l0, h1, l1;
                split2(x0, h0, l0); split2(x1, h1, l1);
                *(__half2*)(g_C_hi + hidx) = __halves2half2(h0, h1);
                *(__half2*)(g_C_lo + hidx) = __halves2half2(l0, l1);
            }
}

// ---------------------------------------------------------------------------
// k2: Z/R = sigmoid(C @ W^T + bias), K=512 (16 chunks), N=128 per CTA.
// BULK pipeline: 4 stages x 24KB, 3 bulk copies per chunk. grid (4, 512).
// ---------------------------------------------------------------------------
#define K2_STAGE 24576
#define K2_MB    98304
#define K2_SMEM  (98304 + 64)
__global__ __launch_bounds__(256, 2) void k2(const float* __restrict__ bias_z,
                                             const float* __restrict__ bias_r) {
    extern __shared__ char sm[];
    const int tid = threadIdx.x, lane = tid & 31, wid = tid >> 5;
    const int wm = wid >> 1, wn = wid & 1;
    const int gate = blockIdx.x >> 1, nb = blockIdx.x & 1, rt = blockIdx.y;

    const char* Ah = (const char*)g_C_hi + (size_t)rt * (16 * 8192);
    const char* Al = (const char*)g_C_lo + (size_t)rt * (16 * 8192);
    const char* Bb = (const char*)(gate ? g_Wr : g_Wz) + (size_t)nb * (16 * 8192);

    const u32 sb = smem_u32(sm);
    const u32 mb0 = sb + K2_MB;

    // blocked-swizzle lane constants
    const u32 arow = (u32)(wm * 32 + (lane & 15)) * 64;
    const u32 aswp = ((((u32)lane & 15) >> 1) & 3) << 4;
    const u32 ahalf = (u32)(lane >> 4);
    const u32 bsl = (u32)((lane & 7) + ((lane >> 4) << 3));
    const u32 brow = (u32)(wn * 64 + bsl) * 64;
    const u32 bswp = ((bsl >> 1) & 3) << 4;
    const u32 bhalf = (u32)((lane >> 3) & 1);

    if (tid == 0) {
#pragma unroll
        for (int s = 0; s < 4; s++) mbar_init(mb0 + s * 8, 1);
        for (int j = 0; j < 3; j++) {
            u32 st = sb + j * K2_STAGE, mb = mb0 + j * 8;
            mbar_expect(mb, K2_STAGE);
            cp_bulk(st,         Ah + (size_t)j * 8192, 8192, mb);
            cp_bulk(st + 8192,  Al + (size_t)j * 8192, 8192, mb);
            cp_bulk(st + 16384, Bb + (size_t)j * 8192, 8192, mb);
        }
    }
    __syncthreads();

    float acc[2][8][4];
    ZERO_ACC8(acc);

    for (int ch = 0; ch < 16; ch++) {
        const int s = ch & 3;
        mbar_wait(mb0 + s * 8, (ch >> 2) & 1);
        __syncthreads();
        if (tid == 0 && ch + 3 < 16) {
            int j = ch + 3;
            u32 st = sb + (j & 3) * K2_STAGE, mb = mb0 + (j & 3) * 8;
            mbar_expect(mb, K2_STAGE);
            cp_bulk(st,         Ah + (size_t)j * 8192, 8192, mb);
            cp_bulk(st + 8192,  Al + (size_t)j * 8192, 8192, mb);
            cp_bulk(st + 16384, Bb + (size_t)j * 8192, 8192, mb);
        }
        const u32 sA = sb + s * K2_STAGE, sL = sA + 8192, sB = sA + 16384;
#pragma unroll
        for (int k16 = 0; k16 < 2; k16++) {
            const u32 goffA = (((2 * k16 + ahalf) << 4) ^ aswp);
            const u32 goffB = (((2 * k16 + bhalf) << 4) ^ bswp);
            u32 bf[4][4];
#pragma unroll
            for (int q = 0; q < 4; q++)
                ldsm4(bf[q], sB + brow + q * 1024 + goffB);
            u32 ah[2][4], al[2][4];
#pragma unroll
            for (int mi = 0; mi < 2; mi++) {
                ldsm4(ah[mi], sA + arow + mi * 1024 + goffA);
                ldsm4(al[mi], sL + arow + mi * 1024 + goffA);
            }
#pragma unroll
            for (int mi = 0; mi < 2; mi++)
#pragma unroll
                for (int ni = 0; ni < 8; ni++)
                    mma16816(acc[mi][ni], ah[mi], &bf[ni >> 1][(ni & 1) * 2]);
#pragma unroll
            for (int mi = 0; mi < 2; mi++)
#pragma unroll
                for (int ni = 0; ni < 8; ni++)
                    mma16816(acc[mi][ni], al[mi], &bf[ni >> 1][(ni & 1) * 2]);
        }
    }

    float* out = gate ? g_R : g_Z;
    const float* bias = gate ? bias_r : bias_z;
#pragma unroll
    for (int mi = 0; mi < 2; mi++)
#pragma unroll
        for (int ni = 0; ni < 8; ni++)
#pragma unroll
            for (int hh = 0; hh < 2; hh++) {
                int lr = wm * 32 + mi * 16 + (lane >> 2) + hh * 8;
                int c  = nb * 128 + wn * 64 + ni * 8 + (lane & 3) * 2;
                float2 bb = *(const float2*)(bias + (size_t)lr * 256 + c);
                float2 o;
                o.x = sigmoidf_fast(acc[mi][ni][hh * 2]     + bb.x);
                o.y = sigmoidf_fast(acc[mi][ni][hh * 2 + 1] + bb.y);
                *(float2*)(out + ((size_t)rt * 128 + lr) * 256 + c) = o;
            }
}

// ---------------------------------------------------------------------------
// k3: acc = AH@Wh2 (8) ; acc *= r ; acc += AX@Wh1 (8) ; GRU epilogue.
// A via BULK (blocked C), B via cp.async (padded Wh). grid (2 nb, 512 rt).
// ---------------------------------------------------------------------------
#define K3_STAGE 26624
#define K3_MB    106496
#define K3_SMEM  (106496 + 64)
__global__ __launch_bounds__(256, 2) void k3(const float* __restrict__ bias_h,
                                             const float* __restrict__ hidden,
                                             float* __restrict__ Out) {
    extern __shared__ char sm[];
    const int tid = threadIdx.x, lane = tid & 31, wid = tid >> 5;
    const int wm = wid >> 1, wn = wid & 1;
    const int nb = blockIdx.x, rt = blockIdx.y;

    const char* Ah = (const char*)g_C_hi + (size_t)rt * (16 * 8192);
    const char* Al = (const char*)g_C_lo + (size_t)rt * (16 * 8192);
    const __half* W2 = g_Wh2 + (size_t)nb * 128 * 256;
    const __half* W1 = g_Wh1 + (size_t)nb * 128 * 256;

    const u32 sb = smem_u32(sm);
    const u32 mb0 = sb + K3_MB;

    const u32 arow = (u32)(wm * 32 + (lane & 15)) * 64;
    const u32 aswp = ((((u32)lane & 15) >> 1) & 3) << 4;
    const u32 ahalf = (u32)(lane >> 4);
    const u32 boff = (u32)((wn * 64 + (lane & 7) + ((lane >> 4) << 3)) * STRB + ((lane >> 3) & 1) * 16);

    // chunk j: j<8 -> C kc 8+j with Wh2 ; j>=8 -> C kc j-8 with Wh1
    auto fillA = [&](int j) {
        int kc = (j < 8) ? (8 + j) : (j - 8);
        u32 st = sb + (j & 3) * K3_STAGE, mb = mb0 + (j & 3) * 8;
        mbar_expect(mb, 16384);
        cp_bulk(st,        Ah + (size_t)kc * 8192, 8192, mb);
        cp_bulk(st + 8192, Al + (size_t)kc * 8192, 8192, mb);
    };
    auto fillB = [&](int j) {
        const __half* Bn = ((j < 8) ? W2 : W1) + ((j < 8) ? j : (j - 8)) * 32;
        cp_tile(sb + (j & 3) * K3_STAGE + 16384, Bn, 128, 256, tid);
        cp_commit();
    };

    if (tid == 0) {
#pragma unroll
        for (int s = 0; s < 4; s++) mbar_init(mb0 + s * 8, 1);
        fillA(0); fillA(1); fillA(2);
    }
    fillB(0); fillB(1); fillB(2);
    __syncthreads();

    float acc[2][8][4];
    ZERO_ACC8(acc);

    for (int j = 0; j < 16; j++) {
        const int s = j & 3;
        mbar_wait(mb0 + s * 8, (j >> 2) & 1);
        if (j <= 13) cp_wait<2>(); else if (j == 14) cp_wait<1>(); else cp_wait<0>();
        __syncthreads();
        if (j + 3 < 16) {
            fillB(j + 3);
            if (tid == 0) fillA(j + 3);
        }
        const u32 sA = sb + s * K3_STAGE, sL = sA + 8192, sB = sA + 16384;
#pragma unroll
        for (int k16 = 0; k16 < 2; k16++) {
            const u32 goffA = (((2 * k16 + ahalf) << 4) ^ aswp);
            u32 bf[4][4];
#pragma unroll
            for (int q = 0; q < 4; q++)
                ldsm4(bf[q], sB + boff + q * (16 * STRB) + k16 * 32);
            u32 ah[2][4], al[2][4];
#pragma unroll
            for (int mi = 0; mi < 2; mi++) {
                ldsm4(ah[mi], sA + arow + mi * 1024 + goffA);
                ldsm4(al[mi], sL + arow + mi * 1024 + goffA);
            }
#pragma unroll
            for (int mi = 0; mi < 2; mi++)
#pragma unroll
                for (int ni = 0; ni < 8; ni++)
                    mma16816(acc[mi][ni], ah[mi], &bf[ni >> 1][(ni & 1) * 2]);
#pragma unroll
            for (int mi = 0; mi < 2; mi++)
#pragma unroll
                for (int ni = 0; ni < 8; ni++)
                    mma16816(acc[mi][ni], al[mi], &bf[ni >> 1][(ni & 1) * 2]);
        }
        if (j == 7) {
#pragma unroll
            for (int mi = 0; mi < 2; mi++)
#pragma unroll
                for (int ni = 0; ni < 8; ni++)
#pragma unroll
                    for (int hh = 0; hh < 2; hh++) {
                        int lr = wm * 32 + mi * 16 + (lane >> 2) + hh * 8;
                        int c  = nb * 128 + wn * 64 + ni * 8 + (lane & 3) * 2;
                        float2 rv = *(const float2*)(g_R + ((size_t)rt * 128 + lr) * 256 + c);
                        acc[mi][ni][hh * 2]     *= rv.x;
                        acc[mi][ni][hh * 2 + 1] *= rv.y;
                    }
        }
    }

#pragma unroll
    for (int mi = 0; mi < 2; mi++)
#pragma unroll
        for (int ni = 0; ni < 8; ni++)
#pragma unroll
            for (int hh = 0; hh < 2; hh++) {
                int lr = wm * 32 + mi * 16 + (lane >> 2) + hh * 8;
                int c  = nb * 128 + wn * 64 + ni * 8 + (lane & 3) * 2;
                size_t off = ((size_t)rt * 128 + lr) * 256 + c;
                float2 zv = *(const float2*)(g_Z + off);
                float2 hv = *(const float2*)(hidden + off);
                float2 bv = *(const float2*)(bias_h + (size_t)lr * 256 + c);
                float t0 = tanhf(acc[mi][ni][hh * 2]     + bv.x);
                float t1 = tanhf(acc[mi][ni][hh * 2 + 1] + bv.y);
                float2 o;
                o.x = zv.x * hv.x + (1.0f - zv.x) * t0;
                o.y = zv.y * hv.y + (1.0f - zv.y) * t1;
                *(float2*)(Out + off) = o;
            }
}

// ---------------------------------------------------------------------------
extern "C" void kernel_launch(void* const* d_in, const int* in_sizes, int n_in,
                              void* d_out, int out_size) {
    (void)in_sizes; (void)n_in; (void)out_size;
    const float* X      = (const float*)d_in[0];
    const float* A      = (const float*)d_in[1];
    const float* hidden = (const float*)d_in[2];
    const float* Wz1    = (const float*)d_in[3];
    const float* Wz2    = (const float*)d_in[4];
    const float* Wr1    = (const float*)d_in[5];
    const float* Wr2    = (const float*)d_in[6];
    const float* Wh1    = (const float*)d_in[7];
    const float* Wh2    = (const float*)d_in[8];
    const float* bz     = (const float*)d_in[9];
    const float* br     = (const float*)d_in[10];
    const float* bh     = (const float*)d_in[11];
    float* out          = (float*)d_out;

    static bool attr_done = false;
    if (!attr_done) {
        cudaFuncSetAttribute(k1, cudaFuncAttributeMaxDynamicSharedMemorySize, K1_SMEM);
        cudaFuncSetAttribute(k2, cudaFuncAttributeMaxDynamicSharedMemorySize, K2_SMEM);
        cudaFuncSetAttribute(k3, cudaFuncAttributeMaxDynamicSharedMemorySize, K3_SMEM);
        attr_done = true;
    }

    conv_A<<<8192, 256>>>(A);
    conv_XH<<<dim3(8, 4, 1024), 256>>>(X, hidden);
    conv_W<<<dim3(8, 8, 6), 256>>>(Wz1, Wz2, Wr1, Wr2, Wh1, Wh2);

    k1<<<dim3(4, 512), 256, K1_SMEM>>>();
    k2<<<dim3(4, 512), 256, K2_SMEM>>>(bz, br);
    k3<<<dim3(2, 512), 256, K3_SMEM>>>(bh, hidden, out);
}

// round 12
// speedup vs baseline: 1.2510x; 1.0033x over previous
#include <cuda_runtime.h>
#include <cuda_fp16.h>

typedef unsigned int u32;

#define B_    512
#define ROWS  65536   // B_*128

// ---------------------------------------------------------------------------
// Device-global scratch (allocation-free rule)
// BLOCKED layout (8KB / 4KB blocks, XOR swizzle within):
//   byte_in_block = row*64 + ((col*2) ^ (((row>>1)&3)<<4))
// g_A_hi/lo : [b][kc:4][128 row][32 k]
// g_Xt/g_Ht : [b][kc:4][256 feat][32 tok]
// g_C_hi/lo : [rt*16+kc][128 row][32 k]
// g_Wz/g_Wr : [nb*16+kc][128 n][32 k]
// ---------------------------------------------------------------------------
__device__ __align__(128) __half g_A_hi[(size_t)B_ * 128 * 128];
__device__ __align__(128) __half g_A_lo[(size_t)B_ * 128 * 128];
__device__ __align__(128) __half g_Xt[(size_t)B_ * 256 * 128];
__device__ __align__(128) __half g_Ht[(size_t)B_ * 256 * 128];
__device__ __align__(128) __half g_C_hi[(size_t)ROWS * 512];
__device__ __align__(128) __half g_C_lo[(size_t)ROWS * 512];
__device__ float  g_Z[(size_t)ROWS * 256];
__device__ float  g_R[(size_t)ROWS * 256];
__device__ __align__(128) __half g_Wz[256 * 512];
__device__ __align__(128) __half g_Wr[256 * 512];
__device__ __half g_Wh1[256 * 256];                 // [n][k] (k3 path, unblocked)
__device__ __half g_Wh2[256 * 256];

// ---------------------------------------------------------------------------
// Helpers
// ---------------------------------------------------------------------------
__device__ __forceinline__ u32 smem_u32(const void* p) {
    u32 a;
    asm("{ .reg .u64 t; cvta.to.shared.u64 t, %1; cvt.u32.u64 %0, t; }" : "=r"(a) : "l"(p));
    return a;
}
__device__ __forceinline__ void ldsm4(u32* r, u32 addr) {
    asm volatile("ldmatrix.sync.aligned.m8n8.x4.shared.b16 {%0,%1,%2,%3}, [%4];"
                 : "=r"(r[0]), "=r"(r[1]), "=r"(r[2]), "=r"(r[3]) : "r"(addr));
}
__device__ __forceinline__ void mma16816(float* d, const u32* a, const u32* b) {
    asm volatile(
        "mma.sync.aligned.m16n8k16.row.col.f32.f16.f16.f32 "
        "{%0,%1,%2,%3}, {%4,%5,%6,%7}, {%8,%9}, {%0,%1,%2,%3};"
        : "+f"(d[0]), "+f"(d[1]), "+f"(d[2]), "+f"(d[3])
        : "r"(a[0]), "r"(a[1]), "r"(a[2]), "r"(a[3]), "r"(b[0]), "r"(b[1]));
}
__device__ __forceinline__ float sigmoidf_fast(float x) {
    return 1.0f / (1.0f + __expf(-x));
}
__device__ __forceinline__ void split2(float x, __half& h, __half& l) {
    h = __float2half_rn(x);
    l = __float2half_rn(x - __half2float(h));
}
__device__ __forceinline__ void cp16(u32 sdst, const void* gsrc) {
    asm volatile(
        "{ .reg .u64 p; cvta.to.global.u64 p, %1; cp.async.cg.shared.global [%0], [p], 16; }"
        :: "r"(sdst), "l"(gsrc) : "memory");
}
__device__ __forceinline__ void cp_commit() {
    asm volatile("cp.async.commit_group;" ::: "memory");
}
template <int N>
__device__ __forceinline__ void cp_wait() {
    asm volatile("cp.async.wait_group %0;" :: "n"(N) : "memory");
}
// ---- bulk DMA + mbarrier ----
__device__ __forceinline__ void cp_bulk(u32 sdst, const void* gsrc, u32 bytes, u32 mbar) {
    asm volatile(
        "{ .reg .u64 p; cvta.to.global.u64 p, %1;\n\t"
        "cp.async.bulk.shared::cluster.global.mbarrier::complete_tx::bytes [%0], [p], %2, [%3]; }"
        :: "r"(sdst), "l"(gsrc), "r"(bytes), "r"(mbar) : "memory");
}
__device__ __forceinline__ void mbar_init(u32 addr, u32 cnt) {
    asm volatile("mbarrier.init.shared.b64 [%0], %1;" :: "r"(addr), "r"(cnt) : "memory");
}
__device__ __forceinline__ void mbar_expect(u32 addr, u32 bytes) {
    asm volatile("mbarrier.arrive.expect_tx.shared::cta.b64 _, [%0], %1;"
                 :: "r"(addr), "r"(bytes) : "memory");
}
__device__ __forceinline__ void mbar_wait(u32 addr, u32 parity) {
    asm volatile(
        "{\n\t.reg .pred P;\n\t"
        "WAIT_%=:\n\t"
        "mbarrier.try_wait.parity.acquire.cta.shared::cta.b64 P, [%0], %1, 0x989680;\n\t"
        "@!P bra.uni WAIT_%=;\n\t}"
        :: "r"(addr), "r"(parity) : "memory");
}

#define STRB 80   // padded staging for k3's Wh tile

__device__ __forceinline__ void cp_tile(u32 sdst, const __half* g, int rows, int gs, int tid) {
    int total = rows * 4;
    for (int i = tid; i < total; i += 256) {
        int r = i >> 2, c = i & 3;
        cp16(sdst + r * STRB + c * 16, g + (size_t)r * gs + c * 8);
    }
}

#define ZERO_ACC8(acc) \
    _Pragma("unroll") for (int _a = 0; _a < 2; _a++) \
    _Pragma("unroll") for (int _c = 0; _c < 8; _c++) \
    _Pragma("unroll") for (int _d = 0; _d < 4; _d++) acc[_a][_c][_d] = 0.0f;

// ---------------------------------------------------------------------------
// Conversion kernels
// ---------------------------------------------------------------------------
// A -> blocked+swizzled hi/lo. Thread handles 4 consecutive cols (same 16B group).
__global__ __launch_bounds__(256) void conv_A(const float* __restrict__ A) {
    size_t i = ((size_t)blockIdx.x * 256 + threadIdx.x) * 4;
    float4 v = *(const float4*)(A + i);
    int b   = (int)(i >> 14);
    int rem = (int)(i & 16383);
    int row = rem >> 7, col = rem & 127;
    int kc = col >> 5, kk = col & 31;
    __half h0, h1, h2, h3, l0, l1, l2, l3;
    split2(v.x, h0, l0); split2(v.y, h1, l1); split2(v.z, h2, l2); split2(v.w, h3, l3);
    __half2 hv0 = __halves2half2(h0, h1), hv1 = __halves2half2(h2, h3);
    __half2 lv0 = __halves2half2(l0, l1), lv1 = __halves2half2(l2, l3);
    u32 swo = (u32)((kk * 2) ^ (((row >> 1) & 3) << 4));   // byte offset in row
    size_t hidx = (size_t)(b * 4 + kc) * 4096 + (size_t)row * 32 + (swo >> 1);
    *(__half2*)(g_A_hi + hidx)     = hv0;
    *(__half2*)(g_A_hi + hidx + 2) = hv1;
    *(__half2*)(g_A_lo + hidx)     = lv0;
    *(__half2*)(g_A_lo + hidx + 2) = lv1;
}

// X/H transpose -> blocked+swizzled [b][kc][256 feat][32 tok]
__global__ __launch_bounds__(256) void conv_XH(const float* __restrict__ X,
                                               const float* __restrict__ Hd) {
    int z = blockIdx.z;
    int b = z & (B_ - 1);
    const float* src = (z < B_) ? X : Hd;
    __half* dst = (z < B_) ? g_Xt : g_Ht;
    __shared__ float s[32][33];
    int tx = threadIdx.x & 31, ty = threadIdx.x >> 5;
    int f0 = blockIdx.x * 32, t0 = blockIdx.y * 32;
    const float* sp = src + (size_t)b * 128 * 256;
#pragma unroll
    for (int r = 0; r < 4; r++)
        s[ty + 8 * r][tx] = sp[(size_t)(t0 + ty + 8 * r) * 256 + f0 + tx];
    __syncthreads();
#pragma unroll
    for (int r = 0; r < 4; r++) {
        int feat = f0 + ty + 8 * r;
        int tok  = t0 + tx;
        int kc = tok >> 5, tk = tok & 31;
        u32 swo = (u32)((tk * 2) ^ (((feat >> 1) & 3) << 4));
        size_t idx = ((size_t)(b * 4 + kc) * 256 + feat) * 32 + (swo >> 1);
        dst[idx] = __float2half_rn(s[tx][ty + 8 * r]);
    }
}

// jobs 0-3 write BLOCKED+swizzled g_Wz/g_Wr; jobs 4-5 plain [n][k] Wh.
__global__ __launch_bounds__(256) void conv_W(const float* __restrict__ Wz1, const float* __restrict__ Wz2,
                                              const float* __restrict__ Wr1, const float* __restrict__ Wr2,
                                              const float* __restrict__ Wh1, const float* __restrict__ Wh2) {
    int job = blockIdx.z;
    const float* src; __half* dst; int koff; bool blocked;
    switch (job) {
        case 0:  src = Wz1; dst = g_Wz;  koff = 0;   blocked = true;  break;
        case 1:  src = Wz2; dst = g_Wz;  koff = 256; blocked = true;  break;
        case 2:  src = Wr1; dst = g_Wr;  koff = 0;   blocked = true;  break;
        case 3:  src = Wr2; dst = g_Wr;  koff = 256; blocked = true;  break;
        case 4:  src = Wh1; dst = g_Wh1; koff = 0;   blocked = false; break;
        default: src = Wh2; dst = g_Wh2; koff = 0;   blocked = false; break;
    }
    __shared__ float s[32][33];
    int tx = threadIdx.x & 31, ty = threadIdx.x >> 5;
    int n0 = blockIdx.x * 32, k0 = blockIdx.y * 32;
#pragma unroll
    for (int r = 0; r < 4; r++)
        s[ty + 8 * r][tx] = src[(size_t)(k0 + ty + 8 * r) * 256 + n0 + tx];
    __syncthreads();
#pragma unroll
    for (int r = 0; r < 4; r++) {
        int n = n0 + ty + 8 * r;
        int k = koff + k0 + tx;
        __half h = __float2half_rn(s[tx][ty + 8 * r]);
        if (blocked) {
            int nb = n >> 7, nr = n & 127, kc = k >> 5, kk = k & 31;
            size_t hidx = (size_t)(nb * 16 + kc) * 4096 + nr * 32
                        + ((((kk * 2) ^ (((nr >> 1) & 3) << 4))) >> 1);
            dst[hidx] = h;
        } else {
            dst[(size_t)n * 256 + k] = h;
        }
    }
}

// ---------------------------------------------------------------------------
// k1: per (nb, b): C[128 tok, 128 cols] (X feats nb*64.. | H feats nb*64..).
// ALL-BULK: 4 stages x 24KB == 4 chunks; everything issued up front.
// grid (4, 512), 256 thr, 2 CTA/SM.
// ---------------------------------------------------------------------------
#define K1_STAGE 24576
#define K1_MB    98304
#define K1_SMEM  (98304 + 64)
__global__ __launch_bounds__(256, 2) void k1() {
    extern __shared__ char sm[];
    const int tid = threadIdx.x, lane = tid & 31, wid = tid >> 5;
    const int wm = wid >> 1, wn = wid & 1;
    const int nb = blockIdx.x, b = blockIdx.y;

    const char* Ah = (const char*)g_A_hi + (size_t)b * (4 * 8192);
    const char* Al = (const char*)g_A_lo + (size_t)b * (4 * 8192);
    const char* Bx = (const char*)g_Xt + ((size_t)b * 4 * 256 + (size_t)nb * 64) * 64;
    const char* Bh = (const char*)g_Ht + ((size_t)b * 4 * 256 + (size_t)nb * 64) * 64;

    const u32 sb = smem_u32(sm);
    const u32 mb0 = sb + K1_MB;

    // blocked-swizzle lane constants (same scheme as k2)
    const u32 arow = (u32)(wm * 32 + (lane & 15)) * 64;
    const u32 aswp = ((((u32)lane & 15) >> 1) & 3) << 4;
    const u32 ahalf = (u32)(lane >> 4);
    const u32 bsl = (u32)((lane & 7) + ((lane >> 4) << 3));
    const u32 brow = (u32)(wn * 64 + bsl) * 64;       // wn=0 -> X rows, wn=1 -> H rows
    const u32 bswp = ((bsl >> 1) & 3) << 4;
    const u32 bhalf = (u32)((lane >> 3) & 1);

    if (tid == 0) {
#pragma unroll
        for (int s = 0; s < 4; s++) mbar_init(mb0 + s * 8, 1);
#pragma unroll
        for (int j = 0; j < 4; j++) {
            u32 st = sb + j * K1_STAGE, mb = mb0 + j * 8;
            mbar_expect(mb, K1_STAGE);
            cp_bulk(st,         Ah + (size_t)j * 8192, 8192, mb);
            cp_bulk(st + 8192,  Al + (size_t)j * 8192, 8192, mb);
            cp_bulk(st + 16384,        Bx + (size_t)j * 16384, 4096, mb);  // X: 64 rows of block j
            cp_bulk(st + 16384 + 4096, Bh + (size_t)j * 16384, 4096, mb);  // H: 64 rows of block j
        }
    }
    __syncthreads();

    float acc[2][8][4];
    ZERO_ACC8(acc);

    for (int ch = 0; ch < 4; ch++) {
        mbar_wait(mb0 + ch * 8, 0);
        __syncthreads();
        const u32 sA = sb + ch * K1_STAGE, sL = sA + 8192, sB = sA + 16384;
#pragma unroll
        for (int k16 = 0; k16 < 2; k16++) {
            const u32 goffA = (((2 * k16 + ahalf) << 4) ^ aswp);
            const u32 goffB = (((2 * k16 + bhalf) << 4) ^ bswp);
            u32 bf[4][4];
#pragma unroll
            for (int q = 0; q < 4; q++)
                ldsm4(bf[q], sB + brow + q * 1024 + goffB);
            u32 ah[2][4], al[2][4];
#pragma unroll
            for (int mi = 0; mi < 2; mi++) {
                ldsm4(ah[mi], sA + arow + mi * 1024 + goffA);
                ldsm4(al[mi], sL + arow + mi * 1024 + goffA);
            }
#pragma unroll
            for (int mi = 0; mi < 2; mi++)
#pragma unroll
                for (int ni = 0; ni < 8; ni++)
                    mma16816(acc[mi][ni], ah[mi], &bf[ni >> 1][(ni & 1) * 2]);
#pragma unroll
            for (int mi = 0; mi < 2; mi++)
#pragma unroll
                for (int ni = 0; ni < 8; ni++)
                    mma16816(acc[mi][ni], al[mi], &bf[ni >> 1][(ni & 1) * 2]);
        }
    }

    const size_t cb_base = (size_t)b * (16 * 4096);   // half units
    const int colb = (wn == 0) ? (nb * 64) : (256 + nb * 64);
#pragma unroll
    for (int mi = 0; mi < 2; mi++)
#pragma unroll
        for (int ni = 0; ni < 8; ni++)
#pragma unroll
            for (int hh = 0; hh < 2; hh++) {
                int lr = wm * 32 + mi * 16 + (lane >> 2) + hh * 8;
                int c  = colb + ni * 8 + (lane & 3) * 2;
                int kc = c >> 5, cc = c & 31;
                u32 swo = (u32)((cc * 2) ^ (((lr >> 1) & 3) << 4));
                size_t hidx = cb_base + (size_t)kc * 4096 + (size_t)lr * 32 + (swo >> 1);
                float x0 = acc[mi][ni][hh * 2], x1 = acc[mi][ni][hh * 2 + 1];
                __half h0, l0, h1, l1;
                split2(x0, h0, l0); split2(x1, h1, l1);
                *(__half2*)(g_C_hi + hidx) = __halves2half2(h0, h1);
                *(__half2*)(g_C_lo + hidx) = __halves2half2(l0, l1);
            }
}

// ---------------------------------------------------------------------------
// k2: Z/R = sigmoid(C @ W^T + bias), K=512 (16 chunks), N=128 per CTA.
// BULK pipeline: 4 stages x 24KB. grid (4, 512).
// ---------------------------------------------------------------------------
#define K2_STAGE 24576
#define K2_MB    98304
#define K2_SMEM  (98304 + 64)
__global__ __launch_bounds__(256, 2) void k2(const float* __restrict__ bias_z,
                                             const float* __restrict__ bias_r) {
    extern __shared__ char sm[];
    const int tid = threadIdx.x, lane = tid & 31, wid = tid >> 5;
    const int wm = wid >> 1, wn = wid & 1;
    const int gate = blockIdx.x >> 1, nb = blockIdx.x & 1, rt = blockIdx.y;

    const char* Ah = (const char*)g_C_hi + (size_t)rt * (16 * 8192);
    const char* Al = (const char*)g_C_lo + (size_t)rt * (16 * 8192);
    const char* Bb = (const char*)(gate ? g_Wr : g_Wz) + (size_t)nb * (16 * 8192);

    const u32 sb = smem_u32(sm);
    const u32 mb0 = sb + K2_MB;

    const u32 arow = (u32)(wm * 32 + (lane & 15)) * 64;
    const u32 aswp = ((((u32)lane & 15) >> 1) & 3) << 4;
    const u32 ahalf = (u32)(lane >> 4);
    const u32 bsl = (u32)((lane & 7) + ((lane >> 4) << 3));
    const u32 brow = (u32)(wn * 64 + bsl) * 64;
    const u32 bswp = ((bsl >> 1) & 3) << 4;
    const u32 bhalf = (u32)((lane >> 3) & 1);

    if (tid == 0) {
#pragma unroll
        for (int s = 0; s < 4; s++) mbar_init(mb0 + s * 8, 1);
        for (int j = 0; j < 3; j++) {
            u32 st = sb + j * K2_STAGE, mb = mb0 + j * 8;
            mbar_expect(mb, K2_STAGE);
            cp_bulk(st,         Ah + (size_t)j * 8192, 8192, mb);
            cp_bulk(st + 8192,  Al + (size_t)j * 8192, 8192, mb);
            cp_bulk(st + 16384, Bb + (size_t)j * 8192, 8192, mb);
        }
    }
    __syncthreads();

    float acc[2][8][4];
    ZERO_ACC8(acc);

    for (int ch = 0; ch < 16; ch++) {
        const int s = ch & 3;
        mbar_wait(mb0 + s * 8, (ch >> 2) & 1);
        __syncthreads();
        if (tid == 0 && ch + 3 < 16) {
            int j = ch + 3;
            u32 st = sb + (j & 3) * K2_STAGE, mb = mb0 + (j & 3) * 8;
            mbar_expect(mb, K2_STAGE);
            cp_bulk(st,         Ah + (size_t)j * 8192, 8192, mb);
            cp_bulk(st + 8192,  Al + (size_t)j * 8192, 8192, mb);
            cp_bulk(st + 16384, Bb + (size_t)j * 8192, 8192, mb);
        }
        const u32 sA = sb + s * K2_STAGE, sL = sA + 8192, sB = sA + 16384;
#pragma unroll
        for (int k16 = 0; k16 < 2; k16++) {
            const u32 goffA = (((2 * k16 + ahalf) << 4) ^ aswp);
            const u32 goffB = (((2 * k16 + bhalf) << 4) ^ bswp);
            u32 bf[4][4];
#pragma unroll
            for (int q = 0; q < 4; q++)
                ldsm4(bf[q], sB + brow + q * 1024 + goffB);
            u32 ah[2][4], al[2][4];
#pragma unroll
            for (int mi = 0; mi < 2; mi++) {
                ldsm4(ah[mi], sA + arow + mi * 1024 + goffA);
                ldsm4(al[mi], sL + arow + mi * 1024 + goffA);
            }
#pragma unroll
            for (int mi = 0; mi < 2; mi++)
#pragma unroll
                for (int ni = 0; ni < 8; ni++)
                    mma16816(acc[mi][ni], ah[mi], &bf[ni >> 1][(ni & 1) * 2]);
#pragma unroll
            for (int mi = 0; mi < 2; mi++)
#pragma unroll
                for (int ni = 0; ni < 8; ni++)
                    mma16816(acc[mi][ni], al[mi], &bf[ni >> 1][(ni & 1) * 2]);
        }
    }

    float* out = gate ? g_R : g_Z;
    const float* bias = gate ? bias_r : bias_z;
#pragma unroll
    for (int mi = 0; mi < 2; mi++)
#pragma unroll
        for (int ni = 0; ni < 8; ni++)
#pragma unroll
            for (int hh = 0; hh < 2; hh++) {
                int lr = wm * 32 + mi * 16 + (lane >> 2) + hh * 8;
                int c  = nb * 128 + wn * 64 + ni * 8 + (lane & 3) * 2;
                float2 bb = *(const float2*)(bias + (size_t)lr * 256 + c);
                float2 o;
                o.x = sigmoidf_fast(acc[mi][ni][hh * 2]     + bb.x);
                o.y = sigmoidf_fast(acc[mi][ni][hh * 2 + 1] + bb.y);
                *(float2*)(out + ((size_t)rt * 128 + lr) * 256 + c) = o;
            }
}

// ---------------------------------------------------------------------------
// k3: acc = AH@Wh2 (8) ; acc *= r ; acc += AX@Wh1 (8) ; GRU epilogue.
// A via BULK (blocked C), B via cp.async (padded Wh). grid (2 nb, 512 rt).
// ---------------------------------------------------------------------------
#define K3_STAGE 26624
#define K3_MB    106496
#define K3_SMEM  (106496 + 64)
__global__ __launch_bounds__(256, 2) void k3(const float* __restrict__ bias_h,
                                             const float* __restrict__ hidden,
                                             float* __restrict__ Out) {
    extern __shared__ char sm[];
    const int tid = threadIdx.x, lane = tid & 31, wid = tid >> 5;
    const int wm = wid >> 1, wn = wid & 1;
    const int nb = blockIdx.x, rt = blockIdx.y;

    const char* Ah = (const char*)g_C_hi + (size_t)rt * (16 * 8192);
    const char* Al = (const char*)g_C_lo + (size_t)rt * (16 * 8192);
    const __half* W2 = g_Wh2 + (size_t)nb * 128 * 256;
    const __half* W1 = g_Wh1 + (size_t)nb * 128 * 256;

    const u32 sb = smem_u32(sm);
    const u32 mb0 = sb + K3_MB;

    const u32 arow = (u32)(wm * 32 + (lane & 15)) * 64;
    const u32 aswp = ((((u32)lane & 15) >> 1) & 3) << 4;
    const u32 ahalf = (u32)(lane >> 4);
    const u32 boff = (u32)((wn * 64 + (lane & 7) + ((lane >> 4) << 3)) * STRB + ((lane >> 3) & 1) * 16);

    auto fillA = [&](int j) {
        int kc = (j < 8) ? (8 + j) : (j - 8);
        u32 st = sb + (j & 3) * K3_STAGE, mb = mb0 + (j & 3) * 8;
        mbar_expect(mb, 16384);
        cp_bulk(st,        Ah + (size_t)kc * 8192, 8192, mb);
        cp_bulk(st + 8192, Al + (size_t)kc * 8192, 8192, mb);
    };
    auto fillB = [&](int j) {
        const __half* Bn = ((j < 8) ? W2 : W1) + ((j < 8) ? j : (j - 8)) * 32;
        cp_tile(sb + (j & 3) * K3_STAGE + 16384, Bn, 128, 256, tid);
        cp_commit();
    };

    if (tid == 0) {
#pragma unroll
        for (int s = 0; s < 4; s++) mbar_init(mb0 + s * 8, 1);
        fillA(0); fillA(1); fillA(2);
    }
    fillB(0); fillB(1); fillB(2);
    __syncthreads();

    float acc[2][8][4];
    ZERO_ACC8(acc);

    for (int j = 0; j < 16; j++) {
        const int s = j & 3;
        mbar_wait(mb0 + s * 8, (j >> 2) & 1);
        if (j <= 13) cp_wait<2>(); else if (j == 14) cp_wait<1>(); else cp_wait<0>();
        __syncthreads();
        if (j + 3 < 16) {
            fillB(j + 3);
            if (tid == 0) fillA(j + 3);
        }
        const u32 sA = sb + s * K3_STAGE, sL = sA + 8192, sB = sA + 16384;
#pragma unroll
        for (int k16 = 0; k16 < 2; k16++) {
            const u32 goffA = (((2 * k16 + ahalf) << 4) ^ aswp);
            u32 bf[4][4];
#pragma unroll
            for (int q = 0; q < 4; q++)
                ldsm4(bf[q], sB + boff + q * (16 * STRB) + k16 * 32);
            u32 ah[2][4], al[2][4];
#pragma unroll
            for (int mi = 0; mi < 2; mi++) {
                ldsm4(ah[mi], sA + arow + mi * 1024 + goffA);
                ldsm4(al[mi], sL + arow + mi * 1024 + goffA);
            }
#pragma unroll
            for (int mi = 0; mi < 2; mi++)
#pragma unroll
                for (int ni = 0; ni < 8; ni++)
                    mma16816(acc[mi][ni], ah[mi], &bf[ni >> 1][(ni & 1) * 2]);
#pragma unroll
            for (int mi = 0; mi < 2; mi++)
#pragma unroll
                for (int ni = 0; ni < 8; ni++)
                    mma16816(acc[mi][ni], al[mi], &bf[ni >> 1][(ni & 1) * 2]);
        }
        if (j == 7) {
#pragma unroll
            for (int mi = 0; mi < 2; mi++)
#pragma unroll
                for (int ni = 0; ni < 8; ni++)
#pragma unroll
                    for (int hh = 0; hh < 2; hh++) {
                        int lr = wm * 32 + mi * 16 + (lane >> 2) + hh * 8;
                        int c  = nb * 128 + wn * 64 + ni * 8 + (lane & 3) * 2;
                        float2 rv = *(const float2*)(g_R + ((size_t)rt * 128 + lr) * 256 + c);
                        acc[mi][ni][hh * 2]     *= rv.x;
                        acc[mi][ni][hh * 2 + 1] *= rv.y;
                    }
        }
    }

#pragma unroll
    for (int mi = 0; mi < 2; mi++)
#pragma unroll
        for (int ni = 0; ni < 8; ni++)
#pragma unroll
            for (int hh = 0; hh < 2; hh++) {
                int lr = wm * 32 + mi * 16 + (lane >> 2) + hh * 8;
                int c  = nb * 128 + wn * 64 + ni * 8 + (lane & 3) * 2;
                size_t off = ((size_t)rt * 128 + lr) * 256 + c;
                float2 zv = *(const float2*)(g_Z + off);
                float2 hv = *(const float2*)(hidden + off);
                float2 bv = *(const float2*)(bias_h + (size_t)lr * 256 + c);
                float t0 = tanhf(acc[mi][ni][hh * 2]     + bv.x);
                float t1 = tanhf(acc[mi][ni][hh * 2 + 1] + bv.y);
                float2 o;
                o.x = zv.x * hv.x + (1.0f - zv.x) * t0;
                o.y = zv.y * hv.y + (1.0f - zv.y) * t1;
                *(float2*)(Out + off) = o;
            }
}

// ---------------------------------------------------------------------------
extern "C" void kernel_launch(void* const* d_in, const int* in_sizes, int n_in,
                              void* d_out, int out_size) {
    (void)in_sizes; (void)n_in; (void)out_size;
    const float* X      = (const float*)d_in[0];
    const float* A      = (const float*)d_in[1];
    const float* hidden = (const float*)d_in[2];
    const float* Wz1    = (const float*)d_in[3];
    const float* Wz2    = (const float*)d_in[4];
    const float* Wr1    = (const float*)d_in[5];
    const float* Wr2    = (const float*)d_in[6];
    const float* Wh1    = (const float*)d_in[7];
    const float* Wh2    = (const float*)d_in[8];
    const float* bz     = (const float*)d_in[9];
    const float* br     = (const float*)d_in[10];
    const float* bh     = (const float*)d_in[11];
    float* out          = (float*)d_out;

    static bool attr_done = false;
    if (!attr_done) {
        cudaFuncSetAttribute(k1, cudaFuncAttributeMaxDynamicSharedMemorySize, K1_SMEM);
        cudaFuncSetAttribute(k2, cudaFuncAttributeMaxDynamicSharedMemorySize, K2_SMEM);
        cudaFuncSetAttribute(k3, cudaFuncAttributeMaxDynamicSharedMemorySize, K3_SMEM);
        attr_done = true;
    }

    conv_A<<<8192, 256>>>(A);
    conv_XH<<<dim3(8, 4, 1024), 256>>>(X, hidden);
    conv_W<<<dim3(8, 8, 6), 256>>>(Wz1, Wz2, Wr1, Wr2, Wh1, Wh2);

    k1<<<dim3(4, 512), 256, K1_SMEM>>>();
    k2<<<dim3(4, 512), 256, K2_SMEM>>>(bz, br);
    k3<<<dim3(2, 512), 256, K3_SMEM>>>(bh, hidden, out);
}

// round 13
// speedup vs baseline: 1.3172x; 1.0529x over previous
#include <cuda_runtime.h>
#include <cuda_fp16.h>

typedef unsigned int u32;

#define B_    512
#define ROWS  65536   // B_*128

// ---------------------------------------------------------------------------
// Device-global scratch (allocation-free rule)
// HL block = 16KB: [hi: 128 row x 32 k][lo: 128 row x 32 k], swizzled:
//   byte_in_half_block = row*64 + ((col*2) ^ (((row>>1)&3)<<4))
// g_A  : [b][kc:4]  HL blocks
// g_C  : [rt][kc:16] HL blocks
// g_Xt/g_Ht : [b][kc:4][256 feat][32 tok] single-precision-fp16 blocks (8KB)
// g_Wz/g_Wr : [nb:2][kc:16][128 n][32 k] 8KB blocks
// g_Wh1/g_Wh2 : [nb:2][kc:8][128 n][32 k] 8KB blocks
// ---------------------------------------------------------------------------
__device__ __align__(128) __half g_A[(size_t)B_ * 4 * 8192];
__device__ __align__(128) __half g_Xt[(size_t)B_ * 256 * 128];
__device__ __align__(128) __half g_Ht[(size_t)B_ * 256 * 128];
__device__ __align__(128) __half g_C[(size_t)ROWS * 1024];      // 134MB (hi+lo)
__device__ float  g_Z[(size_t)ROWS * 256];
__device__ float  g_R[(size_t)ROWS * 256];
__device__ __align__(128) __half g_Wz[256 * 512];
__device__ __align__(128) __half g_Wr[256 * 512];
__device__ __align__(128) __half g_Wh1[256 * 256];
__device__ __align__(128) __half g_Wh2[256 * 256];

// ---------------------------------------------------------------------------
// Helpers
// ---------------------------------------------------------------------------
__device__ __forceinline__ u32 smem_u32(const void* p) {
    u32 a;
    asm("{ .reg .u64 t; cvta.to.shared.u64 t, %1; cvt.u32.u64 %0, t; }" : "=r"(a) : "l"(p));
    return a;
}
__device__ __forceinline__ void ldsm4(u32* r, u32 addr) {
    asm volatile("ldmatrix.sync.aligned.m8n8.x4.shared.b16 {%0,%1,%2,%3}, [%4];"
                 : "=r"(r[0]), "=r"(r[1]), "=r"(r[2]), "=r"(r[3]) : "r"(addr));
}
__device__ __forceinline__ void mma16816(float* d, const u32* a, const u32* b) {
    asm volatile(
        "mma.sync.aligned.m16n8k16.row.col.f32.f16.f16.f32 "
        "{%0,%1,%2,%3}, {%4,%5,%6,%7}, {%8,%9}, {%0,%1,%2,%3};"
        : "+f"(d[0]), "+f"(d[1]), "+f"(d[2]), "+f"(d[3])
        : "r"(a[0]), "r"(a[1]), "r"(a[2]), "r"(a[3]), "r"(b[0]), "r"(b[1]));
}
__device__ __forceinline__ float sigmoidf_fast(float x) {
    return 1.0f / (1.0f + __expf(-x));
}
__device__ __forceinline__ void split2(float x, __half& h, __half& l) {
    h = __float2half_rn(x);
    l = __float2half_rn(x - __half2float(h));
}
// ---- bulk DMA + mbarrier ----
__device__ __forceinline__ void cp_bulk(u32 sdst, const void* gsrc, u32 bytes, u32 mbar) {
    asm volatile(
        "{ .reg .u64 p; cvta.to.global.u64 p, %1;\n\t"
        "cp.async.bulk.shared::cluster.global.mbarrier::complete_tx::bytes [%0], [p], %2, [%3]; }"
        :: "r"(sdst), "l"(gsrc), "r"(bytes), "r"(mbar) : "memory");
}
__device__ __forceinline__ void mbar_init(u32 addr, u32 cnt) {
    asm volatile("mbarrier.init.shared.b64 [%0], %1;" :: "r"(addr), "r"(cnt) : "memory");
}
__device__ __forceinline__ void mbar_expect(u32 addr, u32 bytes) {
    asm volatile("mbarrier.arrive.expect_tx.shared::cta.b64 _, [%0], %1;"
                 :: "r"(addr), "r"(bytes) : "memory");
}
__device__ __forceinline__ void mbar_wait(u32 addr, u32 parity) {
    asm volatile(
        "{\n\t.reg .pred P;\n\t"
        "WAIT_%=:\n\t"
        "mbarrier.try_wait.parity.acquire.cta.shared::cta.b64 P, [%0], %1, 0x989680;\n\t"
        "@!P bra.uni WAIT_%=;\n\t}"
        :: "r"(addr), "r"(parity) : "memory");
}

#define ZERO_ACC8(acc) \
    _Pragma("unroll") for (int _a = 0; _a < 2; _a++) \
    _Pragma("unroll") for (int _c = 0; _c < 8; _c++) \
    _Pragma("unroll") for (int _d = 0; _d < 4; _d++) acc[_a][_c][_d] = 0.0f;

// ---------------------------------------------------------------------------
// Conversion kernels
// ---------------------------------------------------------------------------
// A -> HL blocks. Thread handles 4 consecutive cols (same 16B swizzle group).
__global__ __launch_bounds__(256) void conv_A(const float* __restrict__ A) {
    size_t i = ((size_t)blockIdx.x * 256 + threadIdx.x) * 4;
    float4 v = *(const float4*)(A + i);
    int b   = (int)(i >> 14);
    int rem = (int)(i & 16383);
    int row = rem >> 7, col = rem & 127;
    int kc = col >> 5, kk = col & 31;
    __half h0, h1, h2, h3, l0, l1, l2, l3;
    split2(v.x, h0, l0); split2(v.y, h1, l1); split2(v.z, h2, l2); split2(v.w, h3, l3);
    u32 swo = (u32)((kk * 2) ^ (((row >> 1) & 3) << 4));
    size_t hidx = (size_t)(b * 4 + kc) * 8192 + (size_t)row * 32 + (swo >> 1);
    *(__half2*)(g_A + hidx)            = __halves2half2(h0, h1);
    *(__half2*)(g_A + hidx + 2)        = __halves2half2(h2, h3);
    *(__half2*)(g_A + hidx + 4096)     = __halves2half2(l0, l1);
    *(__half2*)(g_A + hidx + 4096 + 2) = __halves2half2(l2, l3);
}

// X/H transpose -> blocked+swizzled [b][kc][256 feat][32 tok]
__global__ __launch_bounds__(256) void conv_XH(const float* __restrict__ X,
                                               const float* __restrict__ Hd) {
    int z = blockIdx.z;
    int b = z & (B_ - 1);
    const float* src = (z < B_) ? X : Hd;
    __half* dst = (z < B_) ? g_Xt : g_Ht;
    __shared__ float s[32][33];
    int tx = threadIdx.x & 31, ty = threadIdx.x >> 5;
    int f0 = blockIdx.x * 32, t0 = blockIdx.y * 32;
    const float* sp = src + (size_t)b * 128 * 256;
#pragma unroll
    for (int r = 0; r < 4; r++)
        s[ty + 8 * r][tx] = sp[(size_t)(t0 + ty + 8 * r) * 256 + f0 + tx];
    __syncthreads();
#pragma unroll
    for (int r = 0; r < 4; r++) {
        int feat = f0 + ty + 8 * r;
        int tok  = t0 + tx;
        int kc = tok >> 5, tk = tok & 31;
        u32 swo = (u32)((tk * 2) ^ (((feat >> 1) & 3) << 4));
        size_t idx = ((size_t)(b * 4 + kc) * 256 + feat) * 32 + (swo >> 1);
        dst[idx] = __float2half_rn(s[tx][ty + 8 * r]);
    }
}

// All weights -> BLOCKED+swizzled [nb][kc][128 n][32 k].
__global__ __launch_bounds__(256) void conv_W(const float* __restrict__ Wz1, const float* __restrict__ Wz2,
                                              const float* __restrict__ Wr1, const float* __restrict__ Wr2,
                                              const float* __restrict__ Wh1, const float* __restrict__ Wh2) {
    int job = blockIdx.z;
    const float* src; __half* dst; int koff, kcn;
    switch (job) {
        case 0:  src = Wz1; dst = g_Wz;  koff = 0;   kcn = 16; break;
        case 1:  src = Wz2; dst = g_Wz;  koff = 256; kcn = 16; break;
        case 2:  src = Wr1; dst = g_Wr;  koff = 0;   kcn = 16; break;
        case 3:  src = Wr2; dst = g_Wr;  koff = 256; kcn = 16; break;
        case 4:  src = Wh1; dst = g_Wh1; koff = 0;   kcn = 8;  break;
        default: src = Wh2; dst = g_Wh2; koff = 0;   kcn = 8;  break;
    }
    __shared__ float s[32][33];
    int tx = threadIdx.x & 31, ty = threadIdx.x >> 5;
    int n0 = blockIdx.x * 32, k0 = blockIdx.y * 32;
#pragma unroll
    for (int r = 0; r < 4; r++)
        s[ty + 8 * r][tx] = src[(size_t)(k0 + ty + 8 * r) * 256 + n0 + tx];
    __syncthreads();
#pragma unroll
    for (int r = 0; r < 4; r++) {
        int n = n0 + ty + 8 * r;
        int k = koff + k0 + tx;
        int nb = n >> 7, nr = n & 127, kc = k >> 5, kk = k & 31;
        size_t hidx = (size_t)(nb * kcn + kc) * 4096 + nr * 32
                    + ((((kk * 2) ^ (((nr >> 1) & 3) << 4))) >> 1);
        dst[hidx] = __float2half_rn(s[tx][ty + 8 * r]);
    }
}

// ---------------------------------------------------------------------------
// Shared MMA inner step on one stage (blocked swizzle addressing).
// sA=hi, sL=lo, sB=B base; warp tile 32(M) x 64(N), K=32, split-A 2-term.
// ---------------------------------------------------------------------------
struct LaneCtx {
    u32 arow, aswp, ahalf, brow, bswp, bhalf;
};
__device__ __forceinline__ void mma_stage(float acc[2][8][4], u32 sA, u32 sL, u32 sB,
                                          const LaneCtx& lc) {
#pragma unroll
    for (int k16 = 0; k16 < 2; k16++) {
        const u32 goffA = (((2 * k16 + lc.ahalf) << 4) ^ lc.aswp);
        const u32 goffB = (((2 * k16 + lc.bhalf) << 4) ^ lc.bswp);
        u32 bf[4][4];
#pragma unroll
        for (int q = 0; q < 4; q++)
            ldsm4(bf[q], sB + lc.brow + q * 1024 + goffB);
        u32 ah[2][4], al[2][4];
#pragma unroll
        for (int mi = 0; mi < 2; mi++) {
            ldsm4(ah[mi], sA + lc.arow + mi * 1024 + goffA);
            ldsm4(al[mi], sL + lc.arow + mi * 1024 + goffA);
        }
#pragma unroll
        for (int mi = 0; mi < 2; mi++)
#pragma unroll
            for (int ni = 0; ni < 8; ni++)
                mma16816(acc[mi][ni], ah[mi], &bf[ni >> 1][(ni & 1) * 2]);
#pragma unroll
        for (int mi = 0; mi < 2; mi++)
#pragma unroll
            for (int ni = 0; ni < 8; ni++)
                mma16816(acc[mi][ni], al[mi], &bf[ni >> 1][(ni & 1) * 2]);
    }
}
__device__ __forceinline__ LaneCtx make_ctx(int wm, int wn, int lane) {
    LaneCtx lc;
    lc.arow  = (u32)(wm * 32 + (lane & 15)) * 64;
    lc.aswp  = ((((u32)lane & 15) >> 1) & 3) << 4;
    lc.ahalf = (u32)(lane >> 4);
    u32 bsl  = (u32)((lane & 7) + ((lane >> 4) << 3));
    lc.brow  = (u32)(wn * 64 + bsl) * 64;
    lc.bswp  = ((bsl >> 1) & 3) << 4;
    lc.bhalf = (u32)((lane >> 3) & 1);
    return lc;
}

// ---------------------------------------------------------------------------
// k1: per (nb, b): C[128 tok, 128 cols] (X feats nb*64.. | H feats nb*64..).
// ALL-BULK: 4 stages x 24KB == 4 chunks, issued up front. grid (4, 512).
// ---------------------------------------------------------------------------
#define STAGE 24576
#define MBOFF 98304
#define KSMEM (98304 + 64)
__global__ __launch_bounds__(256, 2) void k1() {
    extern __shared__ char sm[];
    const int tid = threadIdx.x, lane = tid & 31, wid = tid >> 5;
    const int wm = wid >> 1, wn = wid & 1;
    const int nb = blockIdx.x, b = blockIdx.y;

    const char* Ab = (const char*)g_A + (size_t)b * (4 * 16384);
    const char* Bx = (const char*)g_Xt + (size_t)b * 65536 + (size_t)nb * 4096;
    const char* Bh = (const char*)g_Ht + (size_t)b * 65536 + (size_t)nb * 4096;

    const u32 sb = smem_u32(sm);
    const u32 mb0 = sb + MBOFF;
    const LaneCtx lc = make_ctx(wm, wn, lane);

    if (tid == 0) {
#pragma unroll
        for (int s = 0; s < 4; s++) mbar_init(mb0 + s * 8, 1);
#pragma unroll
        for (int j = 0; j < 4; j++) {
            u32 st = sb + j * STAGE, mb = mb0 + j * 8;
            mbar_expect(mb, STAGE);
            cp_bulk(st,                Ab + (size_t)j * 16384, 16384, mb);
            cp_bulk(st + 16384,        Bx + (size_t)j * 16384, 4096, mb);
            cp_bulk(st + 16384 + 4096, Bh + (size_t)j * 16384, 4096, mb);
        }
    }
    __syncthreads();

    float acc[2][8][4];
    ZERO_ACC8(acc);

    for (int ch = 0; ch < 4; ch++) {
        mbar_wait(mb0 + ch * 8, 0);
        __syncthreads();
        const u32 sA = sb + ch * STAGE;
        mma_stage(acc, sA, sA + 8192, sA + 16384, lc);
    }

    const size_t cb_base = (size_t)b * (16 * 8192);   // half units
    const int colb = (wn == 0) ? (nb * 64) : (256 + nb * 64);
#pragma unroll
    for (int mi = 0; mi < 2; mi++)
#pragma unroll
        for (int ni = 0; ni < 8; ni++)
#pragma unroll
            for (int hh = 0; hh < 2; hh++) {
                int lr = wm * 32 + mi * 16 + (lane >> 2) + hh * 8;
                int c  = colb + ni * 8 + (lane & 3) * 2;
                int kc = c >> 5, cc = c & 31;
                u32 swo = (u32)((cc * 2) ^ (((lr >> 1) & 3) << 4));
                size_t hidx = cb_base + (size_t)kc * 8192 + (size_t)lr * 32 + (swo >> 1);
                float x0 = acc[mi][ni][hh * 2], x1 = acc[mi][ni][hh * 2 + 1];
                __half h0, l0, h1, l1;
                split2(x0, h0, l0); split2(x1, h1, l1);
                *(__half2*)(g_C + hidx)        = __halves2half2(h0, h1);
                *(__half2*)(g_C + hidx + 4096) = __halves2half2(l0, l1);
            }
}

// ---------------------------------------------------------------------------
// k2: Z/R = sigmoid(C @ W^T + bias), K=512 (16 chunks), N=128 per CTA.
// grid (4, 512): x = gate*2 + nb. 2 bulks/chunk.
// ---------------------------------------------------------------------------
__global__ __launch_bounds__(256, 2) void k2(const float* __restrict__ bias_z,
                                             const float* __restrict__ bias_r) {
    extern __shared__ char sm[];
    const int tid = threadIdx.x, lane = tid & 31, wid = tid >> 5;
    const int wm = wid >> 1, wn = wid & 1;
    const int gate = blockIdx.x >> 1, nb = blockIdx.x & 1, rt = blockIdx.y;

    const char* Cb = (const char*)g_C + (size_t)rt * (16 * 16384);
    const char* Bb = (const char*)(gate ? g_Wr : g_Wz) + (size_t)nb * (16 * 8192);

    const u32 sb = smem_u32(sm);
    const u32 mb0 = sb + MBOFF;
    const LaneCtx lc = make_ctx(wm, wn, lane);

    if (tid == 0) {
#pragma unroll
        for (int s = 0; s < 4; s++) mbar_init(mb0 + s * 8, 1);
        for (int j = 0; j < 3; j++) {
            u32 st = sb + j * STAGE, mb = mb0 + j * 8;
            mbar_expect(mb, STAGE);
            cp_bulk(st,         Cb + (size_t)j * 16384, 16384, mb);
            cp_bulk(st + 16384, Bb + (size_t)j * 8192, 8192, mb);
        }
    }
    __syncthreads();

    float acc[2][8][4];
    ZERO_ACC8(acc);

    for (int ch = 0; ch < 16; ch++) {
        const int s = ch & 3;
        mbar_wait(mb0 + s * 8, (ch >> 2) & 1);
        __syncthreads();
        if (tid == 0 && ch + 3 < 16) {
            int j = ch + 3;
            u32 st = sb + (j & 3) * STAGE, mb = mb0 + (j & 3) * 8;
            mbar_expect(mb, STAGE);
            cp_bulk(st,         Cb + (size_t)j * 16384, 16384, mb);
            cp_bulk(st + 16384, Bb + (size_t)j * 8192, 8192, mb);
        }
        const u32 sA = sb + s * STAGE;
        mma_stage(acc, sA, sA + 8192, sA + 16384, lc);
    }

    float* out = gate ? g_R : g_Z;
    const float* bias = gate ? bias_r : bias_z;
#pragma unroll
    for (int mi = 0; mi < 2; mi++)
#pragma unroll
        for (int ni = 0; ni < 8; ni++)
#pragma unroll
            for (int hh = 0; hh < 2; hh++) {
                int lr = wm * 32 + mi * 16 + (lane >> 2) + hh * 8;
                int c  = nb * 128 + wn * 64 + ni * 8 + (lane & 3) * 2;
                float2 bb = *(const float2*)(bias + (size_t)lr * 256 + c);
                float2 o;
                o.x = sigmoidf_fast(acc[mi][ni][hh * 2]     + bb.x);
                o.y = sigmoidf_fast(acc[mi][ni][hh * 2 + 1] + bb.y);
                *(float2*)(out + ((size_t)rt * 128 + lr) * 256 + c) = o;
            }
}

// ---------------------------------------------------------------------------
// k3: acc = AH@Wh2 (8) ; acc *= r ; acc += AX@Wh1 (8) ; GRU epilogue.
// ALL-BULK now (blocked Wh). grid (2 nb, 512 rt).
// ---------------------------------------------------------------------------
__global__ __launch_bounds__(256, 2) void k3(const float* __restrict__ bias_h,
                                             const float* __restrict__ hidden,
                                             float* __restrict__ Out) {
    extern __shared__ char sm[];
    const int tid = threadIdx.x, lane = tid & 31, wid = tid >> 5;
    const int wm = wid >> 1, wn = wid & 1;
    const int nb = blockIdx.x, rt = blockIdx.y;

    const char* Cb = (const char*)g_C + (size_t)rt * (16 * 16384);
    const char* W2 = (const char*)g_Wh2 + (size_t)nb * (8 * 8192);
    const char* W1 = (const char*)g_Wh1 + (size_t)nb * (8 * 8192);

    const u32 sb = smem_u32(sm);
    const u32 mb0 = sb + MBOFF;
    const LaneCtx lc = make_ctx(wm, wn, lane);

    // chunk j: j<8 -> C kc 8+j with Wh2 blk j ; j>=8 -> C kc j-8 with Wh1 blk j-8
    auto fill = [&](int j) {
        int kc = (j < 8) ? (8 + j) : (j - 8);
        const char* Wp = (j < 8) ? (W2 + (size_t)j * 8192) : (W1 + (size_t)(j - 8) * 8192);
        u32 st = sb + (j & 3) * STAGE, mb = mb0 + (j & 3) * 8;
        mbar_expect(mb, STAGE);
        cp_bulk(st,         Cb + (size_t)kc * 16384, 16384, mb);
        cp_bulk(st + 16384, Wp, 8192, mb);
    };

    if (tid == 0) {
#pragma unroll
        for (int s = 0; s < 4; s++) mbar_init(mb0 + s * 8, 1);
        fill(0); fill(1); fill(2);
    }
    __syncthreads();

    float acc[2][8][4];
    ZERO_ACC8(acc);

    for (int j = 0; j < 16; j++) {
        const int s = j & 3;
        mbar_wait(mb0 + s * 8, (j >> 2) & 1);
        __syncthreads();
        if (tid == 0 && j + 3 < 16) fill(j + 3);
        const u32 sA = sb + s * STAGE;
        mma_stage(acc, sA, sA + 8192, sA + 16384, lc);
        if (j == 7) {
#pragma unroll
            for (int mi = 0; mi < 2; mi++)
#pragma unroll
                for (int ni = 0; ni < 8; ni++)
#pragma unroll
                    for (int hh = 0; hh < 2; hh++) {
                        int lr = wm * 32 + mi * 16 + (lane >> 2) + hh * 8;
                        int c  = nb * 128 + wn * 64 + ni * 8 + (lane & 3) * 2;
                        float2 rv = *(const float2*)(g_R + ((size_t)rt * 128 + lr) * 256 + c);
                        acc[mi][ni][hh * 2]     *= rv.x;
                        acc[mi][ni][hh * 2 + 1] *= rv.y;
                    }
        }
    }

#pragma unroll
    for (int mi = 0; mi < 2; mi++)
#pragma unroll
        for (int ni = 0; ni < 8; ni++)
#pragma unroll
            for (int hh = 0; hh < 2; hh++) {
                int lr = wm * 32 + mi * 16 + (lane >> 2) + hh * 8;
                int c  = nb * 128 + wn * 64 + ni * 8 + (lane & 3) * 2;
                size_t off = ((size_t)rt * 128 + lr) * 256 + c;
                float2 zv = *(const float2*)(g_Z + off);
                float2 hv = *(const float2*)(hidden + off);
                float2 bv = *(const float2*)(bias_h + (size_t)lr * 256 + c);
                float t0 = tanhf(acc[mi][ni][hh * 2]     + bv.x);
                float t1 = tanhf(acc[mi][ni][hh * 2 + 1] + bv.y);
                float2 o;
                o.x = zv.x * hv.x + (1.0f - zv.x) * t0;
                o.y = zv.y * hv.y + (1.0f - zv.y) * t1;
                *(float2*)(Out + off) = o;
            }
}

// ---------------------------------------------------------------------------
extern "C" void kernel_launch(void* const* d_in, const int* in_sizes, int n_in,
                              void* d_out, int out_size) {
    (void)in_sizes; (void)n_in; (void)out_size;
    const float* X      = (const float*)d_in[0];
    const float* A      = (const float*)d_in[1];
    const float* hidden = (const float*)d_in[2];
    const float* Wz1    = (const float*)d_in[3];
    const float* Wz2    = (const float*)d_in[4];
    const float* Wr1    = (const float*)d_in[5];
    const float* Wr2    = (const float*)d_in[6];
    const float* Wh1    = (const float*)d_in[7];
    const float* Wh2    = (const float*)d_in[8];
    const float* bz     = (const float*)d_in[9];
    const float* br     = (const float*)d_in[10];
    const float* bh     = (const float*)d_in[11];
    float* out          = (float*)d_out;

    static bool attr_done = false;
    if (!attr_done) {
        cudaFuncSetAttribute(k1, cudaFuncAttributeMaxDynamicSharedMemorySize, KSMEM);
        cudaFuncSetAttribute(k2, cudaFuncAttributeMaxDynamicSharedMemorySize, KSMEM);
        cudaFuncSetAttribute(k3, cudaFuncAttributeMaxDynamicSharedMemorySize, KSMEM);
        attr_done = true;
    }

    conv_A<<<8192, 256>>>(A);
    conv_XH<<<dim3(8, 4, 1024), 256>>>(X, hidden);
    conv_W<<<dim3(8, 8, 6), 256>>>(Wz1, Wz2, Wr1, Wr2, Wh1, Wh2);

    k1<<<dim3(4, 512), 256, KSMEM>>>();
    k2<<<dim3(4, 512), 256, KSMEM>>>(bz, br);
    k3<<<dim3(2, 512), 256, KSMEM>>>(bh, hidden, out);
}

// round 14
// speedup vs baseline: 1.3556x; 1.0292x over previous
#include <cuda_runtime.h>
#include <cuda_fp16.h>

typedef unsigned int u32;

#define B_    512
#define ROWS  65536   // B_*128

// ---------------------------------------------------------------------------
// Device-global scratch (allocation-free rule)
// HL block = 16KB: [hi: 128 row x 32 k][lo: 128 row x 32 k], swizzled:
//   byte_in_half_block = row*64 + ((col*2) ^ (((row>>1)&3)<<4))
// g_A  : [b][kc:4]  HL blocks
// g_C  : [rt][kc:16] HL blocks
// g_Xt/g_Ht : [b][kc:4][256 feat][32 tok] fp16 blocks (8KB)
// g_Wz/g_Wr : [nb:2][kc:16][128 n][32 k] 8KB blocks
// g_Wh1/g_Wh2 : [nb:2][kc:8][128 n][32 k] 8KB blocks
// ---------------------------------------------------------------------------
__device__ __align__(128) __half g_A[(size_t)B_ * 4 * 8192];
__device__ __align__(128) __half g_Xt[(size_t)B_ * 256 * 128];
__device__ __align__(128) __half g_Ht[(size_t)B_ * 256 * 128];
__device__ __align__(128) __half g_C[(size_t)ROWS * 1024];      // 134MB (hi+lo)
__device__ float  g_Z[(size_t)ROWS * 256];
__device__ float  g_R[(size_t)ROWS * 256];
__device__ __align__(128) __half g_Wz[256 * 512];
__device__ __align__(128) __half g_Wr[256 * 512];
__device__ __align__(128) __half g_Wh1[256 * 256];
__device__ __align__(128) __half g_Wh2[256 * 256];

// ---------------------------------------------------------------------------
// Helpers
// ---------------------------------------------------------------------------
__device__ __forceinline__ u32 smem_u32(const void* p) {
    u32 a;
    asm("{ .reg .u64 t; cvta.to.shared.u64 t, %1; cvt.u32.u64 %0, t; }" : "=r"(a) : "l"(p));
    return a;
}
__device__ __forceinline__ void ldsm4(u32* r, u32 addr) {
    asm volatile("ldmatrix.sync.aligned.m8n8.x4.shared.b16 {%0,%1,%2,%3}, [%4];"
                 : "=r"(r[0]), "=r"(r[1]), "=r"(r[2]), "=r"(r[3]) : "r"(addr));
}
__device__ __forceinline__ void mma16816(float* d, const u32* a, const u32* b) {
    asm volatile(
        "mma.sync.aligned.m16n8k16.row.col.f32.f16.f16.f32 "
        "{%0,%1,%2,%3}, {%4,%5,%6,%7}, {%8,%9}, {%0,%1,%2,%3};"
        : "+f"(d[0]), "+f"(d[1]), "+f"(d[2]), "+f"(d[3])
        : "r"(a[0]), "r"(a[1]), "r"(a[2]), "r"(a[3]), "r"(b[0]), "r"(b[1]));
}
__device__ __forceinline__ float sigmoidf_fast(float x) {
    return 1.0f / (1.0f + __expf(-x));
}
__device__ __forceinline__ void split2(float x, __half& h, __half& l) {
    h = __float2half_rn(x);
    l = __float2half_rn(x - __half2float(h));
}
// ---- bulk DMA + mbarrier ----
__device__ __forceinline__ void cp_bulk(u32 sdst, const void* gsrc, u32 bytes, u32 mbar) {
    asm volatile(
        "{ .reg .u64 p; cvta.to.global.u64 p, %1;\n\t"
        "cp.async.bulk.shared::cluster.global.mbarrier::complete_tx::bytes [%0], [p], %2, [%3]; }"
        :: "r"(sdst), "l"(gsrc), "r"(bytes), "r"(mbar) : "memory");
}
__device__ __forceinline__ void cp_bulk_store(void* gdst, u32 ssrc, u32 bytes) {
    asm volatile(
        "{ .reg .u64 p; cvta.to.global.u64 p, %0;\n\t"
        "cp.async.bulk.global.shared::cta.bulk_group [p], [%1], %2; }"
        :: "l"(gdst), "r"(ssrc), "r"(bytes) : "memory");
}
__device__ __forceinline__ void bulk_store_commit() {
    asm volatile("cp.async.bulk.commit_group;" ::: "memory");
}
__device__ __forceinline__ void bulk_store_wait0() {
    asm volatile("cp.async.bulk.wait_group 0;" ::: "memory");
}
__device__ __forceinline__ void fence_async_shared() {
    asm volatile("fence.proxy.async.shared::cta;" ::: "memory");
}
__device__ __forceinline__ void mbar_init(u32 addr, u32 cnt) {
    asm volatile("mbarrier.init.shared.b64 [%0], %1;" :: "r"(addr), "r"(cnt) : "memory");
}
__device__ __forceinline__ void mbar_expect(u32 addr, u32 bytes) {
    asm volatile("mbarrier.arrive.expect_tx.shared::cta.b64 _, [%0], %1;"
                 :: "r"(addr), "r"(bytes) : "memory");
}
__device__ __forceinline__ void mbar_wait(u32 addr, u32 parity) {
    asm volatile(
        "{\n\t.reg .pred P;\n\t"
        "WAIT_%=:\n\t"
        "mbarrier.try_wait.parity.acquire.cta.shared::cta.b64 P, [%0], %1, 0x989680;\n\t"
        "@!P bra.uni WAIT_%=;\n\t}"
        :: "r"(addr), "r"(parity) : "memory");
}

#define ZERO_ACC8(acc) \
    _Pragma("unroll") for (int _a = 0; _a < 2; _a++) \
    _Pragma("unroll") for (int _c = 0; _c < 8; _c++) \
    _Pragma("unroll") for (int _d = 0; _d < 4; _d++) acc[_a][_c][_d] = 0.0f;

// ---------------------------------------------------------------------------
// Conversion kernels
// ---------------------------------------------------------------------------
__global__ __launch_bounds__(256) void conv_A(const float* __restrict__ A) {
    size_t i = ((size_t)blockIdx.x * 256 + threadIdx.x) * 4;
    float4 v = *(const float4*)(A + i);
    int b   = (int)(i >> 14);
    int rem = (int)(i & 16383);
    int row = rem >> 7, col = rem & 127;
    int kc = col >> 5, kk = col & 31;
    __half h0, h1, h2, h3, l0, l1, l2, l3;
    split2(v.x, h0, l0); split2(v.y, h1, l1); split2(v.z, h2, l2); split2(v.w, h3, l3);
    u32 swo = (u32)((kk * 2) ^ (((row >> 1) & 3) << 4));
    size_t hidx = (size_t)(b * 4 + kc) * 8192 + (size_t)row * 32 + (swo >> 1);
    *(__half2*)(g_A + hidx)            = __halves2half2(h0, h1);
    *(__half2*)(g_A + hidx + 2)        = __halves2half2(h2, h3);
    *(__half2*)(g_A + hidx + 4096)     = __halves2half2(l0, l1);
    *(__half2*)(g_A + hidx + 4096 + 2) = __halves2half2(l2, l3);
}

__global__ __launch_bounds__(256) void conv_XH(const float* __restrict__ X,
                                               const float* __restrict__ Hd) {
    int z = blockIdx.z;
    int b = z & (B_ - 1);
    const float* src = (z < B_) ? X : Hd;
    __half* dst = (z < B_) ? g_Xt : g_Ht;
    __shared__ float s[32][33];
    int tx = threadIdx.x & 31, ty = threadIdx.x >> 5;
    int f0 = blockIdx.x * 32, t0 = blockIdx.y * 32;
    const float* sp = src + (size_t)b * 128 * 256;
#pragma unroll
    for (int r = 0; r < 4; r++)
        s[ty + 8 * r][tx] = sp[(size_t)(t0 + ty + 8 * r) * 256 + f0 + tx];
    __syncthreads();
#pragma unroll
    for (int r = 0; r < 4; r++) {
        int feat = f0 + ty + 8 * r;
        int tok  = t0 + tx;
        int kc = tok >> 5, tk = tok & 31;
        u32 swo = (u32)((tk * 2) ^ (((feat >> 1) & 3) << 4));
        size_t idx = ((size_t)(b * 4 + kc) * 256 + feat) * 32 + (swo >> 1);
        dst[idx] = __float2half_rn(s[tx][ty + 8 * r]);
    }
}

__global__ __launch_bounds__(256) void conv_W(const float* __restrict__ Wz1, const float* __restrict__ Wz2,
                                              const float* __restrict__ Wr1, const float* __restrict__ Wr2,
                                              const float* __restrict__ Wh1, const float* __restrict__ Wh2) {
    int job = blockIdx.z;
    const float* src; __half* dst; int koff, kcn;
    switch (job) {
        case 0:  src = Wz1; dst = g_Wz;  koff = 0;   kcn = 16; break;
        case 1:  src = Wz2; dst = g_Wz;  koff = 256; kcn = 16; break;
        case 2:  src = Wr1; dst = g_Wr;  koff = 0;   kcn = 16; break;
        case 3:  src = Wr2; dst = g_Wr;  koff = 256; kcn = 16; break;
        case 4:  src = Wh1; dst = g_Wh1; koff = 0;   kcn = 8;  break;
        default: src = Wh2; dst = g_Wh2; koff = 0;   kcn = 8;  break;
    }
    __shared__ float s[32][33];
    int tx = threadIdx.x & 31, ty = threadIdx.x >> 5;
    int n0 = blockIdx.x * 32, k0 = blockIdx.y * 32;
#pragma unroll
    for (int r = 0; r < 4; r++)
        s[ty + 8 * r][tx] = src[(size_t)(k0 + ty + 8 * r) * 256 + n0 + tx];
    __syncthreads();
#pragma unroll
    for (int r = 0; r < 4; r++) {
        int n = n0 + ty + 8 * r;
        int k = koff + k0 + tx;
        int nb = n >> 7, nr = n & 127, kc = k >> 5, kk = k & 31;
        size_t hidx = (size_t)(nb * kcn + kc) * 4096 + nr * 32
                    + ((((kk * 2) ^ (((nr >> 1) & 3) << 4))) >> 1);
        dst[hidx] = __float2half_rn(s[tx][ty + 8 * r]);
    }
}

// ---------------------------------------------------------------------------
// Shared MMA inner step on one stage (blocked swizzle addressing).
// ---------------------------------------------------------------------------
struct LaneCtx {
    u32 arow, aswp, ahalf, brow, bswp, bhalf;
};
__device__ __forceinline__ void mma_stage(float acc[2][8][4], u32 sA, u32 sL, u32 sB,
                                          const LaneCtx& lc) {
#pragma unroll
    for (int k16 = 0; k16 < 2; k16++) {
        const u32 goffA = (((2 * k16 + lc.ahalf) << 4) ^ lc.aswp);
        const u32 goffB = (((2 * k16 + lc.bhalf) << 4) ^ lc.bswp);
        u32 bf[4][4];
#pragma unroll
        for (int q = 0; q < 4; q++)
            ldsm4(bf[q], sB + lc.brow + q * 1024 + goffB);
        u32 ah[2][4], al[2][4];
#pragma unroll
        for (int mi = 0; mi < 2; mi++) {
            ldsm4(ah[mi], sA + lc.arow + mi * 1024 + goffA);
            ldsm4(al[mi], sL + lc.arow + mi * 1024 + goffA);
        }
#pragma unroll
        for (int mi = 0; mi < 2; mi++)
#pragma unroll
            for (int ni = 0; ni < 8; ni++)
                mma16816(acc[mi][ni], ah[mi], &bf[ni >> 1][(ni & 1) * 2]);
#pragma unroll
        for (int mi = 0; mi < 2; mi++)
#pragma unroll
            for (int ni = 0; ni < 8; ni++)
                mma16816(acc[mi][ni], al[mi], &bf[ni >> 1][(ni & 1) * 2]);
    }
}
__device__ __forceinline__ LaneCtx make_ctx(int wm, int wn, int lane) {
    LaneCtx lc;
    lc.arow  = (u32)(wm * 32 + (lane & 15)) * 64;
    lc.aswp  = ((((u32)lane & 15) >> 1) & 3) << 4;
    lc.ahalf = (u32)(lane >> 4);
    u32 bsl  = (u32)((lane & 7) + ((lane >> 4) << 3));
    lc.brow  = (u32)(wn * 64 + bsl) * 64;
    lc.bswp  = ((bsl >> 1) & 3) << 4;
    lc.bhalf = (u32)((lane >> 3) & 1);
    return lc;
}

#define STAGE 24576
#define MBOFF 98304
#define KSMEM (98304 + 64)

// ---------------------------------------------------------------------------
// k1: per (nb, b): C[128 tok, 128 cols] (X feats nb*64.. | H feats nb*64..).
// ALL-BULK loads (4 stages == 4 chunks), SMEM-repack + BULK STORES epilogue.
// grid (4, 512), 256 thr, 2 CTA/SM.
// ---------------------------------------------------------------------------
__global__ __launch_bounds__(256, 2) void k1() {
    extern __shared__ char sm[];
    const int tid = threadIdx.x, lane = tid & 31, wid = tid >> 5;
    const int wm = wid >> 1, wn = wid & 1;
    const int nb = blockIdx.x, b = blockIdx.y;

    const char* Ab = (const char*)g_A + (size_t)b * (4 * 16384);
    const char* Bx = (const char*)g_Xt + (size_t)b * 65536 + (size_t)nb * 4096;
    const char* Bh = (const char*)g_Ht + (size_t)b * 65536 + (size_t)nb * 4096;

    const u32 sb = smem_u32(sm);
    const u32 mb0 = sb + MBOFF;
    const LaneCtx lc = make_ctx(wm, wn, lane);

    if (tid == 0) {
#pragma unroll
        for (int s = 0; s < 4; s++) mbar_init(mb0 + s * 8, 1);
#pragma unroll
        for (int j = 0; j < 4; j++) {
            u32 st = sb + j * STAGE, mb = mb0 + j * 8;
            mbar_expect(mb, STAGE);
            cp_bulk(st,                Ab + (size_t)j * 16384, 16384, mb);
            cp_bulk(st + 16384,        Bx + (size_t)j * 16384, 4096, mb);
            cp_bulk(st + 16384 + 4096, Bh + (size_t)j * 16384, 4096, mb);
        }
    }
    __syncthreads();

    float acc[2][8][4];
    ZERO_ACC8(acc);

    for (int ch = 0; ch < 4; ch++) {
        mbar_wait(mb0 + ch * 8, 0);
        __syncthreads();
        const u32 sA = sb + ch * STAGE;
        mma_stage(acc, sA, sA + 8192, sA + 16384, lc);
    }

    // ---- epilogue: split -> SMEM repack (4 HL blocks, 64KB) -> 4 bulk stores
    __syncthreads();   // all MMAs done; stage buffers reusable
#pragma unroll
    for (int mi = 0; mi < 2; mi++)
#pragma unroll
        for (int ni = 0; ni < 8; ni++)
#pragma unroll
            for (int hh = 0; hh < 2; hh++) {
                int lr = wm * 32 + mi * 16 + (lane >> 2) + hh * 8;
                int cl = wn * 64 + ni * 8 + (lane & 3) * 2;   // 0..127 local col
                int blk = cl >> 5, cc = cl & 31;
                u32 swo = (u32)((cc * 2) ^ (((lr >> 1) & 3) << 4));
                u32 saddr = sb + blk * 16384 + (u32)lr * 64 + swo;
                float x0 = acc[mi][ni][hh * 2], x1 = acc[mi][ni][hh * 2 + 1];
                __half h0, l0, h1, l1;
                split2(x0, h0, l0); split2(x1, h1, l1);
                __half2 hv = __halves2half2(h0, h1);
                __half2 lv = __halves2half2(l0, l1);
                asm volatile("st.shared.b32 [%0], %1;" :: "r"(saddr), "r"(*(u32*)&hv) : "memory");
                asm volatile("st.shared.b32 [%0], %1;" :: "r"(saddr + 8192), "r"(*(u32*)&lv) : "memory");
            }
    __syncthreads();
    if (tid == 0) {
        fence_async_shared();
        char* Cb = (char*)g_C + (size_t)b * (16 * 16384);
#pragma unroll
        for (int blk = 0; blk < 4; blk++) {
            int kc = (blk < 2) ? (2 * nb + blk) : (8 + 2 * nb + (blk - 2));
            cp_bulk_store(Cb + (size_t)kc * 16384, sb + blk * 16384, 16384);
        }
        bulk_store_commit();
        bulk_store_wait0();
    }
}

// ---------------------------------------------------------------------------
// k2: Z/R = sigmoid(C @ W^T + bias), K=512 (16 chunks), N=128 per CTA.
// grid (4, 512): x = gate*2 + nb. 2 bulks/chunk.
// ---------------------------------------------------------------------------
__global__ __launch_bounds__(256, 2) void k2(const float* __restrict__ bias_z,
                                             const float* __restrict__ bias_r) {
    extern __shared__ char sm[];
    const int tid = threadIdx.x, lane = tid & 31, wid = tid >> 5;
    const int wm = wid >> 1, wn = wid & 1;
    const int gate = blockIdx.x >> 1, nb = blockIdx.x & 1, rt = blockIdx.y;

    const char* Cb = (const char*)g_C + (size_t)rt * (16 * 16384);
    const char* Bb = (const char*)(gate ? g_Wr : g_Wz) + (size_t)nb * (16 * 8192);

    const u32 sb = smem_u32(sm);
    const u32 mb0 = sb + MBOFF;
    const LaneCtx lc = make_ctx(wm, wn, lane);

    if (tid == 0) {
#pragma unroll
        for (int s = 0; s < 4; s++) mbar_init(mb0 + s * 8, 1);
        for (int j = 0; j < 3; j++) {
            u32 st = sb + j * STAGE, mb = mb0 + j * 8;
            mbar_expect(mb, STAGE);
            cp_bulk(st,         Cb + (size_t)j * 16384, 16384, mb);
            cp_bulk(st + 16384, Bb + (size_t)j * 8192, 8192, mb);
        }
    }
    __syncthreads();

    float acc[2][8][4];
    ZERO_ACC8(acc);

    for (int ch = 0; ch < 16; ch++) {
        const int s = ch & 3;
        mbar_wait(mb0 + s * 8, (ch >> 2) & 1);
        __syncthreads();
        if (tid == 0 && ch + 3 < 16) {
            int j = ch + 3;
            u32 st = sb + (j & 3) * STAGE, mb = mb0 + (j & 3) * 8;
            mbar_expect(mb, STAGE);
            cp_bulk(st,         Cb + (size_t)j * 16384, 16384, mb);
            cp_bulk(st + 16384, Bb + (size_t)j * 8192, 8192, mb);
        }
        const u32 sA = sb + s * STAGE;
        mma_stage(acc, sA, sA + 8192, sA + 16384, lc);
    }

    float* out = gate ? g_R : g_Z;
    const float* bias = gate ? bias_r : bias_z;
#pragma unroll
    for (int mi = 0; mi < 2; mi++)
#pragma unroll
        for (int ni = 0; ni < 8; ni++)
#pragma unroll
            for (int hh = 0; hh < 2; hh++) {
                int lr = wm * 32 + mi * 16 + (lane >> 2) + hh * 8;
                int c  = nb * 128 + wn * 64 + ni * 8 + (lane & 3) * 2;
                float2 bb = *(const float2*)(bias + (size_t)lr * 256 + c);
                float2 o;
                o.x = sigmoidf_fast(acc[mi][ni][hh * 2]     + bb.x);
                o.y = sigmoidf_fast(acc[mi][ni][hh * 2 + 1] + bb.y);
                *(float2*)(out + ((size_t)rt * 128 + lr) * 256 + c) = o;
            }
}

// ---------------------------------------------------------------------------
// k3: acc = AH@Wh2 (8) ; acc *= r ; acc += AX@Wh1 (8) ; GRU epilogue.
// ALL-BULK. grid (2 nb, 512 rt).
// ---------------------------------------------------------------------------
__global__ __launch_bounds__(256, 2) void k3(const float* __restrict__ bias_h,
                                             const float* __restrict__ hidden,
                                             float* __restrict__ Out) {
    extern __shared__ char sm[];
    const int tid = threadIdx.x, lane = tid & 31, wid = tid >> 5;
    const int wm = wid >> 1, wn = wid & 1;
    const int nb = blockIdx.x, rt = blockIdx.y;

    const char* Cb = (const char*)g_C + (size_t)rt * (16 * 16384);
    const char* W2 = (const char*)g_Wh2 + (size_t)nb * (8 * 8192);
    const char* W1 = (const char*)g_Wh1 + (size_t)nb * (8 * 8192);

    const u32 sb = smem_u32(sm);
    const u32 mb0 = sb + MBOFF;
    const LaneCtx lc = make_ctx(wm, wn, lane);

    auto fill = [&](int j) {
        int kc = (j < 8) ? (8 + j) : (j - 8);
        const char* Wp = (j < 8) ? (W2 + (size_t)j * 8192) : (W1 + (size_t)(j - 8) * 8192);
        u32 st = sb + (j & 3) * STAGE, mb = mb0 + (j & 3) * 8;
        mbar_expect(mb, STAGE);
        cp_bulk(st,         Cb + (size_t)kc * 16384, 16384, mb);
        cp_bulk(st + 16384, Wp, 8192, mb);
    };

    if (tid == 0) {
#pragma unroll
        for (int s = 0; s < 4; s++) mbar_init(mb0 + s * 8, 1);
        fill(0); fill(1); fill(2);
    }
    __syncthreads();

    float acc[2][8][4];
    ZERO_ACC8(acc);

    for (int j = 0; j < 16; j++) {
        const int s = j & 3;
        mbar_wait(mb0 + s * 8, (j >> 2) & 1);
        __syncthreads();
        if (tid == 0 && j + 3 < 16) fill(j + 3);
        const u32 sA = sb + s * STAGE;
        mma_stage(acc, sA, sA + 8192, sA + 16384, lc);
        if (j == 7) {
#pragma unroll
            for (int mi = 0; mi < 2; mi++)
#pragma unroll
                for (int ni = 0; ni < 8; ni++)
#pragma unroll
                    for (int hh = 0; hh < 2; hh++) {
                        int lr = wm * 32 + mi * 16 + (lane >> 2) + hh * 8;
                        int c  = nb * 128 + wn * 64 + ni * 8 + (lane & 3) * 2;
                        float2 rv = *(const float2*)(g_R + ((size_t)rt * 128 + lr) * 256 + c);
                        acc[mi][ni][hh * 2]     *= rv.x;
                        acc[mi][ni][hh * 2 + 1] *= rv.y;
                    }
        }
    }

#pragma unroll
    for (int mi = 0; mi < 2; mi++)
#pragma unroll
        for (int ni = 0; ni < 8; ni++)
#pragma unroll
            for (int hh = 0; hh < 2; hh++) {
                int lr = wm * 32 + mi * 16 + (lane >> 2) + hh * 8;
                int c  = nb * 128 + wn * 64 + ni * 8 + (lane & 3) * 2;
                size_t off = ((size_t)rt * 128 + lr) * 256 + c;
                float2 zv = *(const float2*)(g_Z + off);
                float2 hv = *(const float2*)(hidden + off);
                float2 bv = *(const float2*)(bias_h + (size_t)lr * 256 + c);
                float t0 = tanhf(acc[mi][ni][hh * 2]     + bv.x);
                float t1 = tanhf(acc[mi][ni][hh * 2 + 1] + bv.y);
                float2 o;
                o.x = zv.x * hv.x + (1.0f - zv.x) * t0;
                o.y = zv.y * hv.y + (1.0f - zv.y) * t1;
                *(float2*)(Out + off) = o;
            }
}

// ---------------------------------------------------------------------------
extern "C" void kernel_launch(void* const* d_in, const int* in_sizes, int n_in,
                              void* d_out, int out_size) {
    (void)in_sizes; (void)n_in; (void)out_size;
    const float* X      = (const float*)d_in[0];
    const float* A      = (const float*)d_in[1];
    const float* hidden = (const float*)d_in[2];
    const float* Wz1    = (const float*)d_in[3];
    const float* Wz2    = (const float*)d_in[4];
    const float* Wr1    = (const float*)d_in[5];
    const float* Wr2    = (const float*)d_in[6];
    const float* Wh1    = (const float*)d_in[7];
    const float* Wh2    = (const float*)d_in[8];
    const float* bz     = (const float*)d_in[9];
    const float* br     = (const float*)d_in[10];
    const float* bh     = (const float*)d_in[11];
    float* out          = (float*)d_out;

    static bool attr_done = false;
    if (!attr_done) {
        cudaFuncSetAttribute(k1, cudaFuncAttributeMaxDynamicSharedMemorySize, KSMEM);
        cudaFuncSetAttribute(k2, cudaFuncAttributeMaxDynamicSharedMemorySize, KSMEM);
        cudaFuncSetAttribute(k3, cudaFuncAttributeMaxDynamicSharedMemorySize, KSMEM);
        attr_done = true;
    }

    conv_A<<<8192, 256>>>(A);
    conv_XH<<<dim3(8, 4, 1024), 256>>>(X, hidden);
    conv_W<<<dim3(8, 8, 6), 256>>>(Wz1, Wz2, Wr1, Wr2, Wh1, Wh2);

    k1<<<dim3(4, 512), 256, KSMEM>>>();
    k2<<<dim3(4, 512), 256, KSMEM>>>(bz, br);
    k3<<<dim3(2, 512), 256, KSMEM>>>(bh, hidden, out);
}